// round 1
// baseline (speedup 1.0000x reference)
#include <cuda_runtime.h>
#include <cuda_bf16.h>
#include <cstdint>

#define NU 70000
#define NI 30000
#define NN 100000   // NU+NI
#define RR 3
#define DD 64
#define EE 1600000
#define NROWS (NN*RR)          // 300000

// output layout (f32, flattened tuple)
#define OFF_U   ((size_t)0)
#define OFF_I   ((size_t)NU*192)                    // 13,440,000
#define OFF_RELA (OFF_I + (size_t)(NI+1)*192)       // 19,200,192
#define OFF_S1  (OFF_RELA + 192)                    // 19,200,384
#define OFF_S2  (OFF_S1 + NU)                       // 19,270,384

// -------- scratch (device globals; no allocation allowed) --------
__device__ float g_ego [(size_t)NN*RR*DD];
__device__ float g_prop[(size_t)NN*RR*DD];
__device__ float g_est [(size_t)NN*RR*DD];
__device__ float g_all [(size_t)NN*RR*DD];
__device__ float g_rela[3*RR*DD];   // rela[0..2], each 3x64

__device__ __forceinline__ float lrelu(float x){ return x > 0.f ? x : 0.01f*x; }

// ---------------- init: ego = all = broadcast(concat(user,item)) ----------------
__global__ __launch_bounds__(256) void k_init(const float* __restrict__ ue,
                                              const float* __restrict__ ie){
    int t = blockIdx.x*256 + threadIdx.x;           // over NN*16 float4
    if (t >= NN*16) return;
    int n = t >> 4, q = t & 15;
    const float4* src = (const float4*)(n < NU ? ue + (size_t)n*64 : ie + (size_t)(n-NU)*64);
    float4 v = src[q];
    #pragma unroll
    for (int r = 0; r < 3; r++){
        ((float4*)(g_ego + ((size_t)n*3 + r)*64))[q] = v;
        ((float4*)(g_all + ((size_t)n*3 + r)*64))[q] = v;
    }
}

// ---------------- rela chain + rela_out ----------------
__global__ void k_rela(const float* __restrict__ rel_emb,
                       const float* __restrict__ Wrel,
                       float* __restrict__ out_rela){
    __shared__ float s0[192], s1[192], s2[192];
    int j = threadIdx.x;                            // 64 threads
    #pragma unroll
    for (int i = 0; i < 3; i++) s0[i*64+j] = rel_emb[i*64+j];
    __syncthreads();
    #pragma unroll
    for (int i = 0; i < 3; i++){
        float a = 0.f;
        #pragma unroll
        for (int d = 0; d < 64; d++) a += s0[i*64+d]*Wrel[d*64+j];
        s1[i*64+j] = a;
    }
    __syncthreads();
    #pragma unroll
    for (int i = 0; i < 3; i++){
        float a = 0.f;
        #pragma unroll
        for (int d = 0; d < 64; d++) a += s1[i*64+d]*Wrel[4096 + d*64+j];
        s2[i*64+j] = a;
    }
    __syncthreads();
    #pragma unroll
    for (int i = 0; i < 3; i++){
        g_rela[        i*64+j] = s0[i*64+j];
        g_rela[192   + i*64+j] = s1[i*64+j];
        g_rela[384   + i*64+j] = s2[i*64+j];
        out_rela[i*64+j] = (s0[i*64+j] + s1[i*64+j] + s2[i*64+j]) * (1.f/3.f);
    }
}

// ---------------- zero prop ----------------
__global__ __launch_bounds__(256) void k_zero(){
    int t = blockIdx.x*256 + threadIdx.x;           // over NN*RR*16 float4
    if (t >= NN*RR*16) return;
    ((float4*)g_prop)[t] = make_float4(0.f,0.f,0.f,0.f);
}

// ---------------- edge scatter: prop[row,rel,:] += ego[col,rel,:]*val ----------------
__global__ __launch_bounds__(256) void k_scatter(const float* __restrict__ vals,
                                                 const int*   __restrict__ rows,
                                                 const int*   __restrict__ cols){
    int rel  = blockIdx.y;
    int gid  = blockIdx.x*256 + threadIdx.x;
    int e    = gid >> 4;
    if (e >= EE) return;
    int lane = gid & 15;
    int base = rel*EE + e;
    int c = __ldg(cols + base);
    int r = __ldg(rows + base);
    float v = __ldg(vals + base);
    float4 m = *(const float4*)(g_ego + ((size_t)c*3 + rel)*64 + lane*4);
    m.x *= v; m.y *= v; m.z *= v; m.w *= v;
    float* dst = g_prop + ((size_t)r*3 + rel)*64 + lane*4;
    asm volatile("red.global.add.v4.f32 [%0], {%1,%2,%3,%4};"
                 :: "l"(dst), "f"(m.x), "f"(m.y), "f"(m.z), "f"(m.w) : "memory");
}

// ---------------- est = leaky_relu((prop .* rela[k]) @ Wgc[k]) ----------------
// M=300000, K=N=64 GEMM, 64-row blocks, 4x4 register tiles
__global__ __launch_bounds__(256) void k_transform(const float* __restrict__ Wgc, int k){
    __shared__ __align__(16) float Ws[64*64];
    __shared__ __align__(16) float As[64*68];
    __shared__ __align__(16) float srel[192];
    int tid = threadIdx.x;
    #pragma unroll
    for (int i = 0; i < 4; i++)
        ((float4*)Ws)[tid + i*256] = ((const float4*)Wgc)[tid + i*256];
    if (tid < 48) ((float4*)srel)[tid] = ((const float4*)(g_rela + k*192))[tid];
    __syncthreads();
    int row0 = blockIdx.x*64;
    #pragma unroll
    for (int i = 0; i < 16; i++){
        int flat = i*256 + tid;
        int rl = flat >> 6, c = flat & 63;
        int row = row0 + rl;
        float a = 0.f;
        if (row < NROWS) a = g_prop[(size_t)row*64 + c] * srel[(row%3)*64 + c];
        As[c*68 + rl] = a;
    }
    __syncthreads();
    int tx = tid & 15, ty = tid >> 4;
    float acc[4][4] = {};
    #pragma unroll
    for (int d = 0; d < 64; d++){
        float4 a = *(const float4*)&As[d*68 + ty*4];
        float4 b = *(const float4*)&Ws[d*64 + tx*4];
        float av[4] = {a.x,a.y,a.z,a.w};
        float bv[4] = {b.x,b.y,b.z,b.w};
        #pragma unroll
        for (int ii = 0; ii < 4; ii++)
            #pragma unroll
            for (int jj = 0; jj < 4; jj++)
                acc[ii][jj] += av[ii]*bv[jj];
    }
    #pragma unroll
    for (int ii = 0; ii < 4; ii++){
        int row = row0 + ty*4 + ii;
        if (row < NROWS){
            float4 o;
            o.x = lrelu(acc[ii][0]); o.y = lrelu(acc[ii][1]);
            o.z = lrelu(acc[ii][2]); o.w = lrelu(acc[ii][3]);
            *(float4*)(g_est + (size_t)row*64 + tx*4) = o;
        }
    }
}

#define WARP_SUM(x) { _Pragma("unroll") for (int _o = 16; _o; _o >>= 1) x += __shfl_xor_sync(0xffffffffu, x, _o); }

// ---------------- per-node attention: ego = softmax(est est^T * s) est; all += ego ----
__global__ __launch_bounds__(256) void k_attn(float scale){
    int gw = (blockIdx.x*256 + threadIdx.x) >> 5;
    int lane = threadIdx.x & 31;
    if (gw >= NN) return;
    size_t base = (size_t)gw*192 + lane*2;
    float2 e0 = *(float2*)(g_est + base);
    float2 e1 = *(float2*)(g_est + base + 64);
    float2 e2 = *(float2*)(g_est + base + 128);
    float g00 = e0.x*e0.x + e0.y*e0.y;
    float g01 = e0.x*e1.x + e0.y*e1.y;
    float g02 = e0.x*e2.x + e0.y*e2.y;
    float g11 = e1.x*e1.x + e1.y*e1.y;
    float g12 = e1.x*e2.x + e1.y*e2.y;
    float g22 = e2.x*e2.x + e2.y*e2.y;
    WARP_SUM(g00); WARP_SUM(g01); WARP_SUM(g02);
    WARP_SUM(g11); WARP_SUM(g12); WARP_SUM(g22);
    float G[3][3] = {{g00,g01,g02},{g01,g11,g12},{g02,g12,g22}};
    #pragma unroll
    for (int r = 0; r < 3; r++){
        float l0 = G[r][0]*scale, l1 = G[r][1]*scale, l2 = G[r][2]*scale;
        float m = fmaxf(l0, fmaxf(l1, l2));
        float w0 = __expf(l0 - m), w1 = __expf(l1 - m), w2 = __expf(l2 - m);
        float inv = 1.f/(w0 + w1 + w2);
        w0 *= inv; w1 *= inv; w2 *= inv;
        float2 o;
        o.x = w0*e0.x + w1*e1.x + w2*e2.x;
        o.y = w0*e0.y + w1*e1.y + w2*e2.y;
        *(float2*)(g_ego + base + r*64) = o;
        float2 al = *(float2*)(g_all + base + r*64);
        al.x += o.x; al.y += o.y;
        *(float2*)(g_all + base + r*64) = al;
    }
}

// ---------------- final attention + write u / i_emb ----------------
__global__ __launch_bounds__(256) void k_final(float* __restrict__ out){
    int gw = (blockIdx.x*256 + threadIdx.x) >> 5;
    int lane = threadIdx.x & 31;
    if (gw > NN) return;
    if (gw == NN){  // padded zero row of i_emb
        float* dst = out + OFF_I + (size_t)NI*192 + lane*2;
        float2 z = make_float2(0.f, 0.f);
        #pragma unroll
        for (int r = 0; r < 3; r++) *(float2*)(dst + r*64) = z;
        return;
    }
    size_t base = (size_t)gw*192 + lane*2;
    float2 a0 = *(float2*)(g_all + base);
    float2 a1 = *(float2*)(g_all + base + 64);
    float2 a2 = *(float2*)(g_all + base + 128);
    float g20 = a2.x*a0.x + a2.y*a0.y;
    float g21 = a2.x*a1.x + a2.y*a1.y;
    float g22 = a2.x*a2.x + a2.y*a2.y;
    WARP_SUM(g20); WARP_SUM(g21); WARP_SUM(g22);
    float m = fmaxf(g20, fmaxf(g21, g22));
    float w0 = __expf(g20 - m), w1 = __expf(g21 - m), w2 = __expf(g22 - m);
    float inv = 1.f/(w0 + w1 + w2);
    w0 *= inv; w1 *= inv; w2 *= inv;
    float2 mid;
    mid.x = w0*a0.x + w1*a1.x + w2*a2.x;
    mid.y = w0*a0.y + w1*a1.y + w2*a2.y;
    const float third = 1.f/3.f;
    float* dst = (gw < NU) ? out + (size_t)gw*192 + lane*2
                           : out + OFF_I + (size_t)(gw-NU)*192 + lane*2;
    *(float2*)(dst)       = make_float2(a0.x*third, a0.y*third);
    *(float2*)(dst + 64)  = make_float2(a1.x*third, a1.y*third);
    *(float2*)(dst + 128) = make_float2(mid.x*third, mid.y*third);
}

// ---------------- GRU gates + scores ----------------
__global__ __launch_bounds__(256) void k_score(const float* __restrict__ u,
                                               const float* __restrict__ gru_w,
                                               const float* __restrict__ gru_b,
                                               const float* __restrict__ tra,
                                               float* __restrict__ s1,
                                               float* __restrict__ s2){
    __shared__ __align__(16) float Ws[64*64];
    __shared__ __align__(16) float As[64*68];
    __shared__ float red1[64*16];
    __shared__ float red2[64*16];
    int tid = threadIdx.x;
    int u0 = blockIdx.x*64;
    int tx = tid & 15, ty = tid >> 4;
    float ps1[4] = {}, ps2[4] = {};
    for (int r = 0; r < 3; r++){
        if (r) __syncthreads();
        #pragma unroll
        for (int i = 0; i < 4; i++)
            ((float4*)Ws)[tid + i*256] = ((const float4*)(gru_w + r*4096))[tid + i*256];
        #pragma unroll
        for (int i = 0; i < 16; i++){
            int flat = i*256 + tid;
            int ul = flat >> 6, c = flat & 63;
            int user = u0 + ul;
            As[c*68 + ul] = (user < NU) ? u[(size_t)user*192 + r*64 + c] : 0.f;
        }
        __syncthreads();
        float acc[4][4] = {};
        #pragma unroll
        for (int d = 0; d < 64; d++){
            float4 a = *(const float4*)&As[d*68 + ty*4];
            float4 b = *(const float4*)&Ws[d*64 + tx*4];
            float av[4] = {a.x,a.y,a.z,a.w};
            float bv[4] = {b.x,b.y,b.z,b.w};
            #pragma unroll
            for (int ii = 0; ii < 4; ii++)
                #pragma unroll
                for (int jj = 0; jj < 4; jj++)
                    acc[ii][jj] += av[ii]*bv[jj];
        }
        #pragma unroll
        for (int ii = 0; ii < 4; ii++){
            #pragma unroll
            for (int jj = 0; jj < 4; jj++){
                int j = tx*4 + jj;
                float uval = As[j*68 + ty*4 + ii];
                float h = uval * (acc[ii][jj] + __ldg(gru_b + r*64 + j));
                if (r == 2){       // tgt feeds both scores, first 64 cols of tra rows
                    ps1[ii] += h*__ldg(tra + j);
                    ps2[ii] += h*__ldg(tra + 128 + j);
                } else if (r == 0){ // aux1 -> score1 upper half
                    ps1[ii] += h*__ldg(tra + 64 + j);
                } else {            // aux2 -> score2 upper half
                    ps2[ii] += h*__ldg(tra + 128 + 64 + j);
                }
            }
        }
    }
    __syncthreads();
    #pragma unroll
    for (int ii = 0; ii < 4; ii++){
        red1[(ty*4+ii)*16 + tx] = ps1[ii];
        red2[(ty*4+ii)*16 + tx] = ps2[ii];
    }
    __syncthreads();
    if (tid < 64){
        float a = 0.f, b = 0.f;
        #pragma unroll
        for (int t = 0; t < 16; t++){ a += red1[tid*16 + t]; b += red2[tid*16 + t]; }
        int user = u0 + tid;
        if (user < NU){ s1[user] = a; s2[user] = b; }
    }
}

extern "C" void kernel_launch(void* const* d_in, const int* in_sizes, int n_in,
                              void* d_out, int out_size){
    const float* user_emb = (const float*)d_in[0];
    const float* item_emb = (const float*)d_in[1];
    const float* rel_emb  = (const float*)d_in[2];
    const float* W_gc     = (const float*)d_in[3];
    const float* W_rel    = (const float*)d_in[4];
    const float* gru_w    = (const float*)d_in[5];
    const float* gru_b    = (const float*)d_in[6];
    const float* tra      = (const float*)d_in[7];
    const float* adj_vals = (const float*)d_in[8];
    const int*   adj_rows = (const int*)  d_in[9];
    const int*   adj_cols = (const int*)  d_in[10];
    float* out = (float*)d_out;

    k_init<<<(NN*16 + 255)/256, 256>>>(user_emb, item_emb);
    k_rela<<<1, 64>>>(rel_emb, W_rel, out + OFF_RELA);

    const float inv_sqrt = 0.08838834764831845f;  // 1/sqrt(128)
    for (int k = 0; k < 2; k++){
        k_zero<<<(NN*RR*16 + 255)/256, 256>>>();
        k_scatter<<<dim3(EE*16/256, 3), 256>>>(adj_vals, adj_rows, adj_cols);
        k_transform<<<(NROWS + 63)/64, 256>>>(W_gc + (size_t)k*4096, k);
        k_attn<<<(NN*32 + 255)/256, 256>>>(inv_sqrt);
    }
    k_final<<<((NN + 1)*32 + 255)/256, 256>>>(out);
    k_score<<<(NU + 63)/64, 256>>>(out, gru_w, gru_b, tra,
                                   out + OFF_S1, out + OFF_S2);
}

// round 2
// speedup vs baseline: 1.1864x; 1.1864x over previous
#include <cuda_runtime.h>
#include <cuda_bf16.h>
#include <cstdint>

#define NU 70000
#define NI 30000
#define NN 100000   // NU+NI
#define RR 3
#define DD 64
#define EE 1600000
#define NROWS (NN*RR)          // 300000

// output layout (f32, flattened tuple)
#define OFF_U   ((size_t)0)
#define OFF_I   ((size_t)NU*192)                    // 13,440,000
#define OFF_RELA (OFF_I + (size_t)(NI+1)*192)       // 19,200,192
#define OFF_S1  (OFF_RELA + 192)                    // 19,200,384
#define OFF_S2  (OFF_S1 + NU)                       // 19,270,384

// -------- scratch (device globals; no allocation allowed) --------
__device__ float g_ego [(size_t)NN*RR*DD];
__device__ float g_prop[(size_t)NN*RR*DD];
__device__ float g_all [(size_t)NN*RR*DD];
__device__ float g_rela[3*RR*DD];   // rela[0..2], each 3x64

__device__ __forceinline__ float lrelu(float x){ return x > 0.f ? x : 0.01f*x; }

// ---------------- init: ego = all = broadcast(concat(user,item)) ----------------
__global__ __launch_bounds__(256) void k_init(const float* __restrict__ ue,
                                              const float* __restrict__ ie){
    int t = blockIdx.x*256 + threadIdx.x;           // over NN*16 float4
    if (t >= NN*16) return;
    int n = t >> 4, q = t & 15;
    const float4* src = (const float4*)(n < NU ? ue + (size_t)n*64 : ie + (size_t)(n-NU)*64);
    float4 v = src[q];
    #pragma unroll
    for (int r = 0; r < 3; r++){
        ((float4*)(g_ego + ((size_t)n*3 + r)*64))[q] = v;
        ((float4*)(g_all + ((size_t)n*3 + r)*64))[q] = v;
    }
}

// ---------------- rela chain + rela_out ----------------
__global__ void k_rela(const float* __restrict__ rel_emb,
                       const float* __restrict__ Wrel,
                       float* __restrict__ out_rela){
    __shared__ float s0[192], s1[192], s2[192];
    int j = threadIdx.x;                            // 64 threads
    #pragma unroll
    for (int i = 0; i < 3; i++) s0[i*64+j] = rel_emb[i*64+j];
    __syncthreads();
    #pragma unroll
    for (int i = 0; i < 3; i++){
        float a = 0.f;
        #pragma unroll
        for (int d = 0; d < 64; d++) a += s0[i*64+d]*Wrel[d*64+j];
        s1[i*64+j] = a;
    }
    __syncthreads();
    #pragma unroll
    for (int i = 0; i < 3; i++){
        float a = 0.f;
        #pragma unroll
        for (int d = 0; d < 64; d++) a += s1[i*64+d]*Wrel[4096 + d*64+j];
        s2[i*64+j] = a;
    }
    __syncthreads();
    #pragma unroll
    for (int i = 0; i < 3; i++){
        g_rela[        i*64+j] = s0[i*64+j];
        g_rela[192   + i*64+j] = s1[i*64+j];
        g_rela[384   + i*64+j] = s2[i*64+j];
        out_rela[i*64+j] = (s0[i*64+j] + s1[i*64+j] + s2[i*64+j]) * (1.f/3.f);
    }
}

// ---------------- zero prop ----------------
__global__ __launch_bounds__(256) void k_zero(){
    int t = blockIdx.x*256 + threadIdx.x;           // over NN*RR*16 float4
    if (t >= NN*RR*16) return;
    ((float4*)g_prop)[t] = make_float4(0.f,0.f,0.f,0.f);
}

// ---------------- edge scatter, 2 edges per thread (MLP=2) ----------------
// prop[row,rel,:] += ego[col,rel,:]*val
__global__ __launch_bounds__(256) void k_scatter(const float* __restrict__ vals,
                                                 const int*   __restrict__ rows,
                                                 const int*   __restrict__ cols){
    int rel  = blockIdx.y;
    int gid  = blockIdx.x*256 + threadIdx.x;
    int e    = gid >> 4;                      // 0 .. EE/2-1
    if (e >= EE/2) return;
    int lane = gid & 15;
    int b0 = rel*EE + e;
    int b1 = b0 + EE/2;
    int c0 = __ldg(cols + b0);
    int c1 = __ldg(cols + b1);
    int r0 = __ldg(rows + b0);
    int r1 = __ldg(rows + b1);
    float v0 = __ldg(vals + b0);
    float v1 = __ldg(vals + b1);
    float4 m0 = *(const float4*)(g_ego + ((size_t)c0*3 + rel)*64 + lane*4);
    float4 m1 = *(const float4*)(g_ego + ((size_t)c1*3 + rel)*64 + lane*4);
    m0.x *= v0; m0.y *= v0; m0.z *= v0; m0.w *= v0;
    m1.x *= v1; m1.y *= v1; m1.z *= v1; m1.w *= v1;
    float* d0 = g_prop + ((size_t)r0*3 + rel)*64 + lane*4;
    float* d1 = g_prop + ((size_t)r1*3 + rel)*64 + lane*4;
    asm volatile("red.global.add.v4.f32 [%0], {%1,%2,%3,%4};"
                 :: "l"(d0), "f"(m0.x), "f"(m0.y), "f"(m0.z), "f"(m0.w) : "memory");
    asm volatile("red.global.add.v4.f32 [%0], {%1,%2,%3,%4};"
                 :: "l"(d1), "f"(m1.x), "f"(m1.y), "f"(m1.z), "f"(m1.w) : "memory");
}

#define WARP_SUM(x) { _Pragma("unroll") for (int _o = 16; _o; _o >>= 1) x += __shfl_xor_sync(0xffffffffu, x, _o); }

// ---------------- fused: est = lrelu((prop.*rela)@Wgc); attn; ego/all update ----
// block = 32 nodes = 96 rows, 384 threads
__global__ __launch_bounds__(384) void k_trans_attn(const float* __restrict__ Wgc,
                                                    int k, float scale){
    __shared__ __align__(16) float Ws[64*64];     // 16KB
    __shared__ __align__(16) float Abuf[6528];    // As: 64x100 (K-major) / est: 96x68
    __shared__ __align__(16) float srel[192];
    int tid = threadIdx.x;
    int n0  = blockIdx.x*32;
    int row0 = n0*3;

    #pragma unroll
    for (int i = 0; i < 3; i++){
        int idx = i*384 + tid;
        if (idx < 1024) ((float4*)Ws)[idx] = ((const float4*)Wgc)[idx];
    }
    if (tid < 192) srel[tid] = g_rela[k*192 + tid];
    // stage A transposed: Abuf[c*100 + rl] = prop[row0+rl][c] * rela[rl%3][c]
    #pragma unroll
    for (int i = 0; i < 16; i++){
        int flat = i*384 + tid;            // 6144 = 96*64
        int rl = flat >> 6, c = flat & 63;
        Abuf[c*100 + rl] = g_prop[(size_t)(row0 + rl)*64 + c] * srel[(rl%3)*64 + c];
    }
    __syncthreads();

    int tx = tid & 15, ty = tid >> 4;      // ty 0..23 (24*4=96 rows), tx*4 cols
    float acc[4][4] = {};
    #pragma unroll
    for (int d = 0; d < 64; d++){
        float4 a = *(const float4*)&Abuf[d*100 + ty*4];
        float4 b = *(const float4*)&Ws[d*64 + tx*4];
        float av[4] = {a.x,a.y,a.z,a.w};
        float bv[4] = {b.x,b.y,b.z,b.w};
        #pragma unroll
        for (int ii = 0; ii < 4; ii++)
            #pragma unroll
            for (int jj = 0; jj < 4; jj++)
                acc[ii][jj] += av[ii]*bv[jj];
    }
    __syncthreads();   // all reads of Abuf done; now reuse as est[96][68]
    #pragma unroll
    for (int ii = 0; ii < 4; ii++){
        float4 o;
        o.x = lrelu(acc[ii][0]); o.y = lrelu(acc[ii][1]);
        o.z = lrelu(acc[ii][2]); o.w = lrelu(acc[ii][3]);
        *(float4*)&Abuf[(ty*4 + ii)*68 + tx*4] = o;
    }
    __syncthreads();

    // attention: 12 warps cover 32 local nodes
    int warp = tid >> 5, lane = tid & 31;
    for (int ln = warp; ln < 32; ln += 12){
        int node = n0 + ln;
        float2 e0 = *(float2*)&Abuf[(3*ln + 0)*68 + lane*2];
        float2 e1 = *(float2*)&Abuf[(3*ln + 1)*68 + lane*2];
        float2 e2 = *(float2*)&Abuf[(3*ln + 2)*68 + lane*2];
        float g00 = e0.x*e0.x + e0.y*e0.y;
        float g01 = e0.x*e1.x + e0.y*e1.y;
        float g02 = e0.x*e2.x + e0.y*e2.y;
        float g11 = e1.x*e1.x + e1.y*e1.y;
        float g12 = e1.x*e2.x + e1.y*e2.y;
        float g22 = e2.x*e2.x + e2.y*e2.y;
        WARP_SUM(g00); WARP_SUM(g01); WARP_SUM(g02);
        WARP_SUM(g11); WARP_SUM(g12); WARP_SUM(g22);
        float G[3][3] = {{g00,g01,g02},{g01,g11,g12},{g02,g12,g22}};
        size_t base = (size_t)node*192 + lane*2;
        #pragma unroll
        for (int r = 0; r < 3; r++){
            float l0 = G[r][0]*scale, l1 = G[r][1]*scale, l2 = G[r][2]*scale;
            float m = fmaxf(l0, fmaxf(l1, l2));
            float w0 = __expf(l0 - m), w1 = __expf(l1 - m), w2 = __expf(l2 - m);
            float inv = 1.f/(w0 + w1 + w2);
            w0 *= inv; w1 *= inv; w2 *= inv;
            float2 o;
            o.x = w0*e0.x + w1*e1.x + w2*e2.x;
            o.y = w0*e0.y + w1*e1.y + w2*e2.y;
            *(float2*)(g_ego + base + r*64) = o;
            float2 al = *(float2*)(g_all + base + r*64);
            al.x += o.x; al.y += o.y;
            *(float2*)(g_all + base + r*64) = al;
        }
    }
}

// ---------------- final attention + write u / i_emb ----------------
__global__ __launch_bounds__(256) void k_final(float* __restrict__ out){
    int gw = (blockIdx.x*256 + threadIdx.x) >> 5;
    int lane = threadIdx.x & 31;
    if (gw > NN) return;
    if (gw == NN){  // padded zero row of i_emb
        float* dst = out + OFF_I + (size_t)NI*192 + lane*2;
        float2 z = make_float2(0.f, 0.f);
        #pragma unroll
        for (int r = 0; r < 3; r++) *(float2*)(dst + r*64) = z;
        return;
    }
    size_t base = (size_t)gw*192 + lane*2;
    float2 a0 = *(float2*)(g_all + base);
    float2 a1 = *(float2*)(g_all + base + 64);
    float2 a2 = *(float2*)(g_all + base + 128);
    float g20 = a2.x*a0.x + a2.y*a0.y;
    float g21 = a2.x*a1.x + a2.y*a1.y;
    float g22 = a2.x*a2.x + a2.y*a2.y;
    WARP_SUM(g20); WARP_SUM(g21); WARP_SUM(g22);
    float m = fmaxf(g20, fmaxf(g21, g22));
    float w0 = __expf(g20 - m), w1 = __expf(g21 - m), w2 = __expf(g22 - m);
    float inv = 1.f/(w0 + w1 + w2);
    w0 *= inv; w1 *= inv; w2 *= inv;
    float2 mid;
    mid.x = w0*a0.x + w1*a1.x + w2*a2.x;
    mid.y = w0*a0.y + w1*a1.y + w2*a2.y;
    const float third = 1.f/3.f;
    float* dst = (gw < NU) ? out + (size_t)gw*192 + lane*2
                           : out + OFF_I + (size_t)(gw-NU)*192 + lane*2;
    *(float2*)(dst)       = make_float2(a0.x*third, a0.y*third);
    *(float2*)(dst + 64)  = make_float2(a1.x*third, a1.y*third);
    *(float2*)(dst + 128) = make_float2(mid.x*third, mid.y*third);
}

// ---------------- GRU gates + scores ----------------
__global__ __launch_bounds__(256) void k_score(const float* __restrict__ u,
                                               const float* __restrict__ gru_w,
                                               const float* __restrict__ gru_b,
                                               const float* __restrict__ tra,
                                               float* __restrict__ s1,
                                               float* __restrict__ s2){
    __shared__ __align__(16) float Ws[64*64];
    __shared__ __align__(16) float As[64*68];
    __shared__ float red1[64*16];
    __shared__ float red2[64*16];
    int tid = threadIdx.x;
    int u0 = blockIdx.x*64;
    int tx = tid & 15, ty = tid >> 4;
    float ps1[4] = {}, ps2[4] = {};
    for (int r = 0; r < 3; r++){
        if (r) __syncthreads();
        #pragma unroll
        for (int i = 0; i < 4; i++)
            ((float4*)Ws)[tid + i*256] = ((const float4*)(gru_w + r*4096))[tid + i*256];
        #pragma unroll
        for (int i = 0; i < 16; i++){
            int flat = i*256 + tid;
            int ul = flat >> 6, c = flat & 63;
            int user = u0 + ul;
            As[c*68 + ul] = (user < NU) ? u[(size_t)user*192 + r*64 + c] : 0.f;
        }
        __syncthreads();
        float acc[4][4] = {};
        #pragma unroll
        for (int d = 0; d < 64; d++){
            float4 a = *(const float4*)&As[d*68 + ty*4];
            float4 b = *(const float4*)&Ws[d*64 + tx*4];
            float av[4] = {a.x,a.y,a.z,a.w};
            float bv[4] = {b.x,b.y,b.z,b.w};
            #pragma unroll
            for (int ii = 0; ii < 4; ii++)
                #pragma unroll
                for (int jj = 0; jj < 4; jj++)
                    acc[ii][jj] += av[ii]*bv[jj];
        }
        #pragma unroll
        for (int ii = 0; ii < 4; ii++){
            #pragma unroll
            for (int jj = 0; jj < 4; jj++){
                int j = tx*4 + jj;
                float uval = As[j*68 + ty*4 + ii];
                float h = uval * (acc[ii][jj] + __ldg(gru_b + r*64 + j));
                if (r == 2){       // tgt feeds both scores
                    ps1[ii] += h*__ldg(tra + j);
                    ps2[ii] += h*__ldg(tra + 128 + j);
                } else if (r == 0){
                    ps1[ii] += h*__ldg(tra + 64 + j);
                } else {
                    ps2[ii] += h*__ldg(tra + 128 + 64 + j);
                }
            }
        }
    }
    __syncthreads();
    #pragma unroll
    for (int ii = 0; ii < 4; ii++){
        red1[(ty*4+ii)*16 + tx] = ps1[ii];
        red2[(ty*4+ii)*16 + tx] = ps2[ii];
    }
    __syncthreads();
    if (tid < 64){
        float a = 0.f, b = 0.f;
        #pragma unroll
        for (int t = 0; t < 16; t++){ a += red1[tid*16 + t]; b += red2[tid*16 + t]; }
        int user = u0 + tid;
        if (user < NU){ s1[user] = a; s2[user] = b; }
    }
}

extern "C" void kernel_launch(void* const* d_in, const int* in_sizes, int n_in,
                              void* d_out, int out_size){
    const float* user_emb = (const float*)d_in[0];
    const float* item_emb = (const float*)d_in[1];
    const float* rel_emb  = (const float*)d_in[2];
    const float* W_gc     = (const float*)d_in[3];
    const float* W_rel    = (const float*)d_in[4];
    const float* gru_w    = (const float*)d_in[5];
    const float* gru_b    = (const float*)d_in[6];
    const float* tra      = (const float*)d_in[7];
    const float* adj_vals = (const float*)d_in[8];
    const int*   adj_rows = (const int*)  d_in[9];
    const int*   adj_cols = (const int*)  d_in[10];
    float* out = (float*)d_out;

    k_init<<<(NN*16 + 255)/256, 256>>>(user_emb, item_emb);
    k_rela<<<1, 64>>>(rel_emb, W_rel, out + OFF_RELA);

    const float inv_sqrt = 0.08838834764831845f;  // 1/sqrt(128)
    for (int k = 0; k < 2; k++){
        k_zero<<<(NN*RR*16 + 255)/256, 256>>>();
        k_scatter<<<dim3((EE/2)*16/256, 3), 256>>>(adj_vals, adj_rows, adj_cols);
        k_trans_attn<<<NN/32, 384>>>(W_gc + (size_t)k*4096, k, inv_sqrt);
    }
    k_final<<<((NN + 1)*32 + 255)/256, 256>>>(out);
    k_score<<<(NU + 63)/64, 256>>>(out, gru_w, gru_b, tra,
                                   out + OFF_S1, out + OFF_S2);
}

// round 3
// speedup vs baseline: 1.2138x; 1.0232x over previous
#include <cuda_runtime.h>
#include <cuda_bf16.h>
#include <cstdint>

#define NU 70000
#define NI 30000
#define NN 100000   // NU+NI
#define RR 3
#define DD 64
#define EE 1600000
#define NROWS (NN*RR)          // 300000

// output layout (f32, flattened tuple)
#define OFF_U   ((size_t)0)
#define OFF_I   ((size_t)NU*192)                    // 13,440,000
#define OFF_RELA (OFF_I + (size_t)(NI+1)*192)       // 19,200,192
#define OFF_S1  (OFF_RELA + 192)                    // 19,200,384
#define OFF_S2  (OFF_S1 + NU)                       // 19,270,384

// -------- scratch (device globals; no allocation allowed) --------
__device__ float g_ego [(size_t)NN*RR*DD];
__device__ float g_prop[(size_t)NN*RR*DD];
__device__ float g_all [(size_t)NN*RR*DD];
__device__ float g_rela[3*RR*DD];   // rela[0..2], each 3x64

__device__ __forceinline__ float lrelu(float x){ return x > 0.f ? x : 0.01f*x; }

// ---------------- init: ego = all = broadcast(concat(user,item)) ----------------
__global__ __launch_bounds__(256) void k_init(const float* __restrict__ ue,
                                              const float* __restrict__ ie){
    int t = blockIdx.x*256 + threadIdx.x;           // over NN*16 float4
    if (t >= NN*16) return;
    int n = t >> 4, q = t & 15;
    const float4* src = (const float4*)(n < NU ? ue + (size_t)n*64 : ie + (size_t)(n-NU)*64);
    float4 v = src[q];
    #pragma unroll
    for (int r = 0; r < 3; r++){
        ((float4*)(g_ego + ((size_t)n*3 + r)*64))[q] = v;
        ((float4*)(g_all + ((size_t)n*3 + r)*64))[q] = v;
    }
}

// ---------------- rela chain + rela_out ----------------
__global__ void k_rela(const float* __restrict__ rel_emb,
                       const float* __restrict__ Wrel,
                       float* __restrict__ out_rela){
    __shared__ float s0[192], s1[192], s2[192];
    int j = threadIdx.x;                            // 64 threads
    #pragma unroll
    for (int i = 0; i < 3; i++) s0[i*64+j] = rel_emb[i*64+j];
    __syncthreads();
    #pragma unroll
    for (int i = 0; i < 3; i++){
        float a = 0.f;
        #pragma unroll
        for (int d = 0; d < 64; d++) a += s0[i*64+d]*Wrel[d*64+j];
        s1[i*64+j] = a;
    }
    __syncthreads();
    #pragma unroll
    for (int i = 0; i < 3; i++){
        float a = 0.f;
        #pragma unroll
        for (int d = 0; d < 64; d++) a += s1[i*64+d]*Wrel[4096 + d*64+j];
        s2[i*64+j] = a;
    }
    __syncthreads();
    #pragma unroll
    for (int i = 0; i < 3; i++){
        g_rela[        i*64+j] = s0[i*64+j];
        g_rela[192   + i*64+j] = s1[i*64+j];
        g_rela[384   + i*64+j] = s2[i*64+j];
        out_rela[i*64+j] = (s0[i*64+j] + s1[i*64+j] + s2[i*64+j]) * (1.f/3.f);
    }
}

// ---------------- zero prop ----------------
__global__ __launch_bounds__(256) void k_zero(){
    int t = blockIdx.x*256 + threadIdx.x;           // over NN*RR*16 float4
    if (t >= NN*RR*16) return;
    ((float4*)g_prop)[t] = make_float4(0.f,0.f,0.f,0.f);
}

// ---------------- edge scatter, 4 edges per thread (MLP=4) ----------------
// prop[row,rel,:] += ego[col,rel,:]*val
#define EQ (EE/4)
__global__ __launch_bounds__(256) void k_scatter(const float* __restrict__ vals,
                                                 const int*   __restrict__ rows,
                                                 const int*   __restrict__ cols){
    int rel  = blockIdx.y;
    int gid  = blockIdx.x*256 + threadIdx.x;
    int e    = gid >> 4;                      // 0 .. EQ-1
    if (e >= EQ) return;
    int lane = gid & 15;
    int b[4];
    #pragma unroll
    for (int q = 0; q < 4; q++) b[q] = rel*EE + e + q*EQ;
    int   c[4], r[4];  float v[4];
    #pragma unroll
    for (int q = 0; q < 4; q++){
        c[q] = __ldg(cols + b[q]);
        r[q] = __ldg(rows + b[q]);
        v[q] = __ldg(vals + b[q]);
    }
    float4 m[4];
    #pragma unroll
    for (int q = 0; q < 4; q++)
        m[q] = *(const float4*)(g_ego + ((size_t)c[q]*3 + rel)*64 + lane*4);
    #pragma unroll
    for (int q = 0; q < 4; q++){
        m[q].x *= v[q]; m[q].y *= v[q]; m[q].z *= v[q]; m[q].w *= v[q];
        float* dst = g_prop + ((size_t)r[q]*3 + rel)*64 + lane*4;
        asm volatile("red.global.add.v4.f32 [%0], {%1,%2,%3,%4};"
                     :: "l"(dst), "f"(m[q].x), "f"(m[q].y), "f"(m[q].z), "f"(m[q].w) : "memory");
    }
}

#define WARP_SUM(x) { _Pragma("unroll") for (int _o = 16; _o; _o >>= 1) x += __shfl_xor_sync(0xffffffffu, x, _o); }

// ---------------- fused: est = lrelu((prop.*rela)@Wgc); attn; ego/all update ----
// block = 32 nodes = 96 rows, 384 threads
__global__ __launch_bounds__(384) void k_trans_attn(const float* __restrict__ Wgc,
                                                    int k, float scale){
    __shared__ __align__(16) float Ws[64*64];     // 16KB
    __shared__ __align__(16) float Abuf[6528];    // As: 64x100 (K-major) / est: 96x68
    __shared__ __align__(16) float srel[192];
    int tid = threadIdx.x;
    int n0  = blockIdx.x*32;
    int row0 = n0*3;

    #pragma unroll
    for (int i = 0; i < 3; i++){
        int idx = i*384 + tid;
        if (idx < 1024) ((float4*)Ws)[idx] = ((const float4*)Wgc)[idx];
    }
    if (tid < 192) srel[tid] = g_rela[k*192 + tid];
    __syncthreads();   // srel must be visible before staging reads it
    // stage A transposed: Abuf[c*100 + rl] = prop[row0+rl][c] * rela[rl%3][c]
    #pragma unroll
    for (int i = 0; i < 16; i++){
        int flat = i*384 + tid;            // 6144 = 96*64
        int rl = flat >> 6, c = flat & 63;
        Abuf[c*100 + rl] = g_prop[(size_t)(row0 + rl)*64 + c] * srel[(rl%3)*64 + c];
    }
    __syncthreads();

    int tx = tid & 15, ty = tid >> 4;      // ty 0..23 (24*4=96 rows), tx*4 cols
    float acc[4][4] = {};
    #pragma unroll
    for (int d = 0; d < 64; d++){
        float4 a = *(const float4*)&Abuf[d*100 + ty*4];
        float4 b = *(const float4*)&Ws[d*64 + tx*4];
        float av[4] = {a.x,a.y,a.z,a.w};
        float bv[4] = {b.x,b.y,b.z,b.w};
        #pragma unroll
        for (int ii = 0; ii < 4; ii++)
            #pragma unroll
            for (int jj = 0; jj < 4; jj++)
                acc[ii][jj] += av[ii]*bv[jj];
    }
    __syncthreads();   // all reads of Abuf done; now reuse as est[96][68]
    #pragma unroll
    for (int ii = 0; ii < 4; ii++){
        float4 o;
        o.x = lrelu(acc[ii][0]); o.y = lrelu(acc[ii][1]);
        o.z = lrelu(acc[ii][2]); o.w = lrelu(acc[ii][3]);
        *(float4*)&Abuf[(ty*4 + ii)*68 + tx*4] = o;
    }
    __syncthreads();

    // attention: 12 warps cover 32 local nodes
    int warp = tid >> 5, lane = tid & 31;
    for (int ln = warp; ln < 32; ln += 12){
        int node = n0 + ln;
        float2 e0 = *(float2*)&Abuf[(3*ln + 0)*68 + lane*2];
        float2 e1 = *(float2*)&Abuf[(3*ln + 1)*68 + lane*2];
        float2 e2 = *(float2*)&Abuf[(3*ln + 2)*68 + lane*2];
        float g00 = e0.x*e0.x + e0.y*e0.y;
        float g01 = e0.x*e1.x + e0.y*e1.y;
        float g02 = e0.x*e2.x + e0.y*e2.y;
        float g11 = e1.x*e1.x + e1.y*e1.y;
        float g12 = e1.x*e2.x + e1.y*e2.y;
        float g22 = e2.x*e2.x + e2.y*e2.y;
        WARP_SUM(g00); WARP_SUM(g01); WARP_SUM(g02);
        WARP_SUM(g11); WARP_SUM(g12); WARP_SUM(g22);
        float G[3][3] = {{g00,g01,g02},{g01,g11,g12},{g02,g12,g22}};
        size_t base = (size_t)node*192 + lane*2;
        #pragma unroll
        for (int r = 0; r < 3; r++){
            float l0 = G[r][0]*scale, l1 = G[r][1]*scale, l2 = G[r][2]*scale;
            float m = fmaxf(l0, fmaxf(l1, l2));
            float w0 = __expf(l0 - m), w1 = __expf(l1 - m), w2 = __expf(l2 - m);
            float inv = 1.f/(w0 + w1 + w2);
            w0 *= inv; w1 *= inv; w2 *= inv;
            float2 o;
            o.x = w0*e0.x + w1*e1.x + w2*e2.x;
            o.y = w0*e0.y + w1*e1.y + w2*e2.y;
            *(float2*)(g_ego + base + r*64) = o;
            float2 al = *(float2*)(g_all + base + r*64);
            al.x += o.x; al.y += o.y;
            *(float2*)(g_all + base + r*64) = al;
        }
    }
}

// ---------------- final attention + write u / i_emb ----------------
__global__ __launch_bounds__(256) void k_final(float* __restrict__ out){
    int gw = (blockIdx.x*256 + threadIdx.x) >> 5;
    int lane = threadIdx.x & 31;
    if (gw > NN) return;
    if (gw == NN){  // padded zero row of i_emb
        float* dst = out + OFF_I + (size_t)NI*192 + lane*2;
        float2 z = make_float2(0.f, 0.f);
        #pragma unroll
        for (int r = 0; r < 3; r++) *(float2*)(dst + r*64) = z;
        return;
    }
    size_t base = (size_t)gw*192 + lane*2;
    float2 a0 = *(float2*)(g_all + base);
    float2 a1 = *(float2*)(g_all + base + 64);
    float2 a2 = *(float2*)(g_all + base + 128);
    float g20 = a2.x*a0.x + a2.y*a0.y;
    float g21 = a2.x*a1.x + a2.y*a1.y;
    float g22 = a2.x*a2.x + a2.y*a2.y;
    WARP_SUM(g20); WARP_SUM(g21); WARP_SUM(g22);
    float m = fmaxf(g20, fmaxf(g21, g22));
    float w0 = __expf(g20 - m), w1 = __expf(g21 - m), w2 = __expf(g22 - m);
    float inv = 1.f/(w0 + w1 + w2);
    w0 *= inv; w1 *= inv; w2 *= inv;
    float2 mid;
    mid.x = w0*a0.x + w1*a1.x + w2*a2.x;
    mid.y = w0*a0.y + w1*a1.y + w2*a2.y;
    const float third = 1.f/3.f;
    float* dst = (gw < NU) ? out + (size_t)gw*192 + lane*2
                           : out + OFF_I + (size_t)(gw-NU)*192 + lane*2;
    *(float2*)(dst)       = make_float2(a0.x*third, a0.y*third);
    *(float2*)(dst + 64)  = make_float2(a1.x*third, a1.y*third);
    *(float2*)(dst + 128) = make_float2(mid.x*third, mid.y*third);
}

// ---------------- GRU gates + scores ----------------
__global__ __launch_bounds__(256) void k_score(const float* __restrict__ u,
                                               const float* __restrict__ gru_w,
                                               const float* __restrict__ gru_b,
                                               const float* __restrict__ tra,
                                               float* __restrict__ s1,
                                               float* __restrict__ s2){
    __shared__ __align__(16) float Ws[64*64];
    __shared__ __align__(16) float As[64*68];
    __shared__ float red1[64*16];
    __shared__ float red2[64*16];
    int tid = threadIdx.x;
    int u0 = blockIdx.x*64;
    int tx = tid & 15, ty = tid >> 4;
    float ps1[4] = {}, ps2[4] = {};
    for (int r = 0; r < 3; r++){
        if (r) __syncthreads();
        #pragma unroll
        for (int i = 0; i < 4; i++)
            ((float4*)Ws)[tid + i*256] = ((const float4*)(gru_w + r*4096))[tid + i*256];
        #pragma unroll
        for (int i = 0; i < 16; i++){
            int flat = i*256 + tid;
            int ul = flat >> 6, c = flat & 63;
            int user = u0 + ul;
            As[c*68 + ul] = (user < NU) ? u[(size_t)user*192 + r*64 + c] : 0.f;
        }
        __syncthreads();
        float acc[4][4] = {};
        #pragma unroll
        for (int d = 0; d < 64; d++){
            float4 a = *(const float4*)&As[d*68 + ty*4];
            float4 b = *(const float4*)&Ws[d*64 + tx*4];
            float av[4] = {a.x,a.y,a.z,a.w};
            float bv[4] = {b.x,b.y,b.z,b.w};
            #pragma unroll
            for (int ii = 0; ii < 4; ii++)
                #pragma unroll
                for (int jj = 0; jj < 4; jj++)
                    acc[ii][jj] += av[ii]*bv[jj];
        }
        #pragma unroll
        for (int ii = 0; ii < 4; ii++){
            #pragma unroll
            for (int jj = 0; jj < 4; jj++){
                int j = tx*4 + jj;
                float uval = As[j*68 + ty*4 + ii];
                float h = uval * (acc[ii][jj] + __ldg(gru_b + r*64 + j));
                if (r == 2){       // tgt feeds both scores
                    ps1[ii] += h*__ldg(tra + j);
                    ps2[ii] += h*__ldg(tra + 128 + j);
                } else if (r == 0){
                    ps1[ii] += h*__ldg(tra + 64 + j);
                } else {
                    ps2[ii] += h*__ldg(tra + 128 + 64 + j);
                }
            }
        }
    }
    __syncthreads();
    #pragma unroll
    for (int ii = 0; ii < 4; ii++){
        red1[(ty*4+ii)*16 + tx] = ps1[ii];
        red2[(ty*4+ii)*16 + tx] = ps2[ii];
    }
    __syncthreads();
    if (tid < 64){
        float a = 0.f, b = 0.f;
        #pragma unroll
        for (int t = 0; t < 16; t++){ a += red1[tid*16 + t]; b += red2[tid*16 + t]; }
        int user = u0 + tid;
        if (user < NU){ s1[user] = a; s2[user] = b; }
    }
}

extern "C" void kernel_launch(void* const* d_in, const int* in_sizes, int n_in,
                              void* d_out, int out_size){
    const float* user_emb = (const float*)d_in[0];
    const float* item_emb = (const float*)d_in[1];
    const float* rel_emb  = (const float*)d_in[2];
    const float* W_gc     = (const float*)d_in[3];
    const float* W_rel    = (const float*)d_in[4];
    const float* gru_w    = (const float*)d_in[5];
    const float* gru_b    = (const float*)d_in[6];
    const float* tra      = (const float*)d_in[7];
    const float* adj_vals = (const float*)d_in[8];
    const int*   adj_rows = (const int*)  d_in[9];
    const int*   adj_cols = (const int*)  d_in[10];
    float* out = (float*)d_out;

    k_init<<<(NN*16 + 255)/256, 256>>>(user_emb, item_emb);
    k_rela<<<1, 64>>>(rel_emb, W_rel, out + OFF_RELA);

    const float inv_sqrt = 0.08838834764831845f;  // 1/sqrt(128)
    for (int k = 0; k < 2; k++){
        k_zero<<<(NN*RR*16 + 255)/256, 256>>>();
        k_scatter<<<dim3(EQ*16/256, 3), 256>>>(adj_vals, adj_rows, adj_cols);
        k_trans_attn<<<NN/32, 384>>>(W_gc + (size_t)k*4096, k, inv_sqrt);
    }
    k_final<<<((NN + 1)*32 + 255)/256, 256>>>(out);
    k_score<<<(NU + 63)/64, 256>>>(out, gru_w, gru_b, tra,
                                   out + OFF_S1, out + OFF_S2);
}

// round 4
// speedup vs baseline: 1.4478x; 1.1928x over previous
#include <cuda_runtime.h>
#include <cuda_bf16.h>
#include <cstdint>

#define NU 70000
#define NI 30000
#define NN 100000   // NU+NI
#define RR 3
#define DD 64
#define EE 1600000
#define NROWS (NN*RR)          // 300000
#define CAP 64                 // bucket capacity per (rel,row)

// output layout (f32, flattened tuple)
#define OFF_U   ((size_t)0)
#define OFF_I   ((size_t)NU*192)                    // 13,440,000
#define OFF_RELA (OFF_I + (size_t)(NI+1)*192)       // 19,200,192
#define OFF_S1  (OFF_RELA + 192)                    // 19,200,384
#define OFF_S2  (OFF_S1 + NU)                       // 19,270,384

// -------- scratch (device globals; no allocation allowed) --------
__device__ float g_ego [(size_t)NN*RR*DD];
__device__ float g_prop[(size_t)NN*RR*DD];
__device__ float g_all [(size_t)NN*RR*DD];
__device__ float g_rela[3*RR*DD];   // rela[0..2], each 3x64
__device__ int   g_cnt [RR*NN];
__device__ __align__(16) int2 g_bkt[(size_t)RR*NN*CAP];   // zero-init; unwritten slots stay (0, 0.0f)

__device__ __forceinline__ float lrelu(float x){ return x > 0.f ? x : 0.01f*x; }

// ---------------- init: ego = all = broadcast(concat(user,item)) ----------------
__global__ __launch_bounds__(256) void k_init(const float* __restrict__ ue,
                                              const float* __restrict__ ie){
    int t = blockIdx.x*256 + threadIdx.x;           // over NN*16 float4
    if (t >= NN*16) return;
    int n = t >> 4, q = t & 15;
    const float4* src = (const float4*)(n < NU ? ue + (size_t)n*64 : ie + (size_t)(n-NU)*64);
    float4 v = src[q];
    #pragma unroll
    for (int r = 0; r < 3; r++){
        ((float4*)(g_ego + ((size_t)n*3 + r)*64))[q] = v;
        ((float4*)(g_all + ((size_t)n*3 + r)*64))[q] = v;
    }
}

// ---------------- rela chain + rela_out ----------------
__global__ void k_rela(const float* __restrict__ rel_emb,
                       const float* __restrict__ Wrel,
                       float* __restrict__ out_rela){
    __shared__ float s0[192], s1[192], s2[192];
    int j = threadIdx.x;                            // 64 threads
    #pragma unroll
    for (int i = 0; i < 3; i++) s0[i*64+j] = rel_emb[i*64+j];
    __syncthreads();
    #pragma unroll
    for (int i = 0; i < 3; i++){
        float a = 0.f;
        #pragma unroll
        for (int d = 0; d < 64; d++) a += s0[i*64+d]*Wrel[d*64+j];
        s1[i*64+j] = a;
    }
    __syncthreads();
    #pragma unroll
    for (int i = 0; i < 3; i++){
        float a = 0.f;
        #pragma unroll
        for (int d = 0; d < 64; d++) a += s1[i*64+d]*Wrel[4096 + d*64+j];
        s2[i*64+j] = a;
    }
    __syncthreads();
    #pragma unroll
    for (int i = 0; i < 3; i++){
        g_rela[        i*64+j] = s0[i*64+j];
        g_rela[192   + i*64+j] = s1[i*64+j];
        g_rela[384   + i*64+j] = s2[i*64+j];
        out_rela[i*64+j] = (s0[i*64+j] + s1[i*64+j] + s2[i*64+j]) * (1.f/3.f);
    }
}

// ---------------- zero bucket counters ----------------
__global__ __launch_bounds__(256) void k_zero_cnt(){
    int t = blockIdx.x*256 + threadIdx.x;
    if (t < RR*NN) g_cnt[t] = 0;
}

// ---------------- bucket build: per (rel,row) edge list ----------------
__global__ __launch_bounds__(256) void k_bucket(const float* __restrict__ vals,
                                                const int*   __restrict__ rows,
                                                const int*   __restrict__ cols){
    int rel = blockIdx.y;
    int e   = blockIdx.x*256 + threadIdx.x;    // 0 .. EE/2-1
    #pragma unroll
    for (int q = 0; q < 2; q++){
        int f = rel*EE + e + q*(EE/2);
        int row = __ldg(rows + f);
        int col = __ldg(cols + f);
        float v = __ldg(vals + f);
        int seg = rel*NN + row;
        int pos = atomicAdd(&g_cnt[seg], 1);
        if (pos < CAP)
            g_bkt[(size_t)seg*CAP + pos] = make_int2(col, __float_as_int(v));
    }
}

// ---------------- gather: prop[row,rel,:] = sum_e ego[col_e,rel,:]*val_e ----------
// 16 lanes per (rel,row); batch 4 edges per iteration for MLP
__global__ __launch_bounds__(256) void k_gather(){
    int rel  = blockIdx.y;
    int grp  = threadIdx.x >> 4;               // 16 groups / block
    int lane = threadIdx.x & 15;
    int row  = blockIdx.x*16 + grp;            // < NN (NN divisible by 16? 100000/16=6250 ✓)
    int seg  = rel*NN + row;
    int cnt  = g_cnt[seg];
    if (cnt > CAP) cnt = CAP;
    const int2* bp = g_bkt + (size_t)seg*CAP;
    float4 acc = make_float4(0.f, 0.f, 0.f, 0.f);
    for (int e = 0; e < cnt; e += 4){
        int4 pa = *(const int4*)(bp + e);       // edges e, e+1   (slots >= cnt are (0,0) => no-op)
        int4 pb = *(const int4*)(bp + e + 2);   // edges e+2, e+3
        const float4 m0 = *(const float4*)(g_ego + ((size_t)pa.x*3 + rel)*64 + lane*4);
        const float4 m1 = *(const float4*)(g_ego + ((size_t)pa.z*3 + rel)*64 + lane*4);
        const float4 m2 = *(const float4*)(g_ego + ((size_t)pb.x*3 + rel)*64 + lane*4);
        const float4 m3 = *(const float4*)(g_ego + ((size_t)pb.z*3 + rel)*64 + lane*4);
        float v0 = __int_as_float(pa.y), v1 = __int_as_float(pa.w);
        float v2 = __int_as_float(pb.y), v3 = __int_as_float(pb.w);
        acc.x = fmaf(m0.x, v0, fmaf(m1.x, v1, fmaf(m2.x, v2, fmaf(m3.x, v3, acc.x))));
        acc.y = fmaf(m0.y, v0, fmaf(m1.y, v1, fmaf(m2.y, v2, fmaf(m3.y, v3, acc.y))));
        acc.z = fmaf(m0.z, v0, fmaf(m1.z, v1, fmaf(m2.z, v2, fmaf(m3.z, v3, acc.z))));
        acc.w = fmaf(m0.w, v0, fmaf(m1.w, v1, fmaf(m2.w, v2, fmaf(m3.w, v3, acc.w))));
    }
    *(float4*)(g_prop + ((size_t)row*3 + rel)*64 + lane*4) = acc;
}

#define WARP_SUM(x) { _Pragma("unroll") for (int _o = 16; _o; _o >>= 1) x += __shfl_xor_sync(0xffffffffu, x, _o); }

// ---------------- fused: est = lrelu((prop.*rela)@Wgc); attn; ego/all update ----
// block = 32 nodes = 96 rows, 384 threads
__global__ __launch_bounds__(384) void k_trans_attn(const float* __restrict__ Wgc,
                                                    int k, float scale){
    __shared__ __align__(16) float Ws[64*64];     // 16KB
    __shared__ __align__(16) float Abuf[6528];    // As: 64x100 (K-major) / est: 96x68
    __shared__ __align__(16) float srel[192];
    int tid = threadIdx.x;
    int n0  = blockIdx.x*32;
    int row0 = n0*3;

    #pragma unroll
    for (int i = 0; i < 3; i++){
        int idx = i*384 + tid;
        if (idx < 1024) ((float4*)Ws)[idx] = ((const float4*)Wgc)[idx];
    }
    if (tid < 192) srel[tid] = g_rela[k*192 + tid];
    __syncthreads();   // srel must be visible before staging reads it
    // stage A transposed: Abuf[c*100 + rl] = prop[row0+rl][c] * rela[rl%3][c]
    #pragma unroll
    for (int i = 0; i < 16; i++){
        int flat = i*384 + tid;            // 6144 = 96*64
        int rl = flat >> 6, c = flat & 63;
        Abuf[c*100 + rl] = g_prop[(size_t)(row0 + rl)*64 + c] * srel[(rl%3)*64 + c];
    }
    __syncthreads();

    int tx = tid & 15, ty = tid >> 4;      // ty 0..23 (24*4=96 rows), tx*4 cols
    float acc[4][4] = {};
    #pragma unroll
    for (int d = 0; d < 64; d++){
        float4 a = *(const float4*)&Abuf[d*100 + ty*4];
        float4 b = *(const float4*)&Ws[d*64 + tx*4];
        float av[4] = {a.x,a.y,a.z,a.w};
        float bv[4] = {b.x,b.y,b.z,b.w};
        #pragma unroll
        for (int ii = 0; ii < 4; ii++)
            #pragma unroll
            for (int jj = 0; jj < 4; jj++)
                acc[ii][jj] += av[ii]*bv[jj];
    }
    __syncthreads();   // all reads of Abuf done; now reuse as est[96][68]
    #pragma unroll
    for (int ii = 0; ii < 4; ii++){
        float4 o;
        o.x = lrelu(acc[ii][0]); o.y = lrelu(acc[ii][1]);
        o.z = lrelu(acc[ii][2]); o.w = lrelu(acc[ii][3]);
        *(float4*)&Abuf[(ty*4 + ii)*68 + tx*4] = o;
    }
    __syncthreads();

    // attention: 12 warps cover 32 local nodes
    int warp = tid >> 5, lane = tid & 31;
    for (int ln = warp; ln < 32; ln += 12){
        int node = n0 + ln;
        float2 e0 = *(float2*)&Abuf[(3*ln + 0)*68 + lane*2];
        float2 e1 = *(float2*)&Abuf[(3*ln + 1)*68 + lane*2];
        float2 e2 = *(float2*)&Abuf[(3*ln + 2)*68 + lane*2];
        float g00 = e0.x*e0.x + e0.y*e0.y;
        float g01 = e0.x*e1.x + e0.y*e1.y;
        float g02 = e0.x*e2.x + e0.y*e2.y;
        float g11 = e1.x*e1.x + e1.y*e1.y;
        float g12 = e1.x*e2.x + e1.y*e2.y;
        float g22 = e2.x*e2.x + e2.y*e2.y;
        WARP_SUM(g00); WARP_SUM(g01); WARP_SUM(g02);
        WARP_SUM(g11); WARP_SUM(g12); WARP_SUM(g22);
        float G[3][3] = {{g00,g01,g02},{g01,g11,g12},{g02,g12,g22}};
        size_t base = (size_t)node*192 + lane*2;
        #pragma unroll
        for (int r = 0; r < 3; r++){
            float l0 = G[r][0]*scale, l1 = G[r][1]*scale, l2 = G[r][2]*scale;
            float m = fmaxf(l0, fmaxf(l1, l2));
            float w0 = __expf(l0 - m), w1 = __expf(l1 - m), w2 = __expf(l2 - m);
            float inv = 1.f/(w0 + w1 + w2);
            w0 *= inv; w1 *= inv; w2 *= inv;
            float2 o;
            o.x = w0*e0.x + w1*e1.x + w2*e2.x;
            o.y = w0*e0.y + w1*e1.y + w2*e2.y;
            *(float2*)(g_ego + base + r*64) = o;
            float2 al = *(float2*)(g_all + base + r*64);
            al.x += o.x; al.y += o.y;
            *(float2*)(g_all + base + r*64) = al;
        }
    }
}

// ---------------- final attention + write u / i_emb ----------------
__global__ __launch_bounds__(256) void k_final(float* __restrict__ out){
    int gw = (blockIdx.x*256 + threadIdx.x) >> 5;
    int lane = threadIdx.x & 31;
    if (gw > NN) return;
    if (gw == NN){  // padded zero row of i_emb
        float* dst = out + OFF_I + (size_t)NI*192 + lane*2;
        float2 z = make_float2(0.f, 0.f);
        #pragma unroll
        for (int r = 0; r < 3; r++) *(float2*)(dst + r*64) = z;
        return;
    }
    size_t base = (size_t)gw*192 + lane*2;
    float2 a0 = *(float2*)(g_all + base);
    float2 a1 = *(float2*)(g_all + base + 64);
    float2 a2 = *(float2*)(g_all + base + 128);
    float g20 = a2.x*a0.x + a2.y*a0.y;
    float g21 = a2.x*a1.x + a2.y*a1.y;
    float g22 = a2.x*a2.x + a2.y*a2.y;
    WARP_SUM(g20); WARP_SUM(g21); WARP_SUM(g22);
    float m = fmaxf(g20, fmaxf(g21, g22));
    float w0 = __expf(g20 - m), w1 = __expf(g21 - m), w2 = __expf(g22 - m);
    float inv = 1.f/(w0 + w1 + w2);
    w0 *= inv; w1 *= inv; w2 *= inv;
    float2 mid;
    mid.x = w0*a0.x + w1*a1.x + w2*a2.x;
    mid.y = w0*a0.y + w1*a1.y + w2*a2.y;
    const float third = 1.f/3.f;
    float* dst = (gw < NU) ? out + (size_t)gw*192 + lane*2
                           : out + OFF_I + (size_t)(gw-NU)*192 + lane*2;
    *(float2*)(dst)       = make_float2(a0.x*third, a0.y*third);
    *(float2*)(dst + 64)  = make_float2(a1.x*third, a1.y*third);
    *(float2*)(dst + 128) = make_float2(mid.x*third, mid.y*third);
}

// ---------------- GRU gates + scores ----------------
__global__ __launch_bounds__(256) void k_score(const float* __restrict__ u,
                                               const float* __restrict__ gru_w,
                                               const float* __restrict__ gru_b,
                                               const float* __restrict__ tra,
                                               float* __restrict__ s1,
                                               float* __restrict__ s2){
    __shared__ __align__(16) float Ws[64*64];
    __shared__ __align__(16) float As[64*68];
    __shared__ float red1[64*16];
    __shared__ float red2[64*16];
    int tid = threadIdx.x;
    int u0 = blockIdx.x*64;
    int tx = tid & 15, ty = tid >> 4;
    float ps1[4] = {}, ps2[4] = {};
    for (int r = 0; r < 3; r++){
        if (r) __syncthreads();
        #pragma unroll
        for (int i = 0; i < 4; i++)
            ((float4*)Ws)[tid + i*256] = ((const float4*)(gru_w + r*4096))[tid + i*256];
        #pragma unroll
        for (int i = 0; i < 16; i++){
            int flat = i*256 + tid;
            int ul = flat >> 6, c = flat & 63;
            int user = u0 + ul;
            As[c*68 + ul] = (user < NU) ? u[(size_t)user*192 + r*64 + c] : 0.f;
        }
        __syncthreads();
        float acc[4][4] = {};
        #pragma unroll
        for (int d = 0; d < 64; d++){
            float4 a = *(const float4*)&As[d*68 + ty*4];
            float4 b = *(const float4*)&Ws[d*64 + tx*4];
            float av[4] = {a.x,a.y,a.z,a.w};
            float bv[4] = {b.x,b.y,b.z,b.w};
            #pragma unroll
            for (int ii = 0; ii < 4; ii++)
                #pragma unroll
                for (int jj = 0; jj < 4; jj++)
                    acc[ii][jj] += av[ii]*bv[jj];
        }
        #pragma unroll
        for (int ii = 0; ii < 4; ii++){
            #pragma unroll
            for (int jj = 0; jj < 4; jj++){
                int j = tx*4 + jj;
                float uval = As[j*68 + ty*4 + ii];
                float h = uval * (acc[ii][jj] + __ldg(gru_b + r*64 + j));
                if (r == 2){       // tgt feeds both scores
                    ps1[ii] += h*__ldg(tra + j);
                    ps2[ii] += h*__ldg(tra + 128 + j);
                } else if (r == 0){
                    ps1[ii] += h*__ldg(tra + 64 + j);
                } else {
                    ps2[ii] += h*__ldg(tra + 128 + 64 + j);
                }
            }
        }
    }
    __syncthreads();
    #pragma unroll
    for (int ii = 0; ii < 4; ii++){
        red1[(ty*4+ii)*16 + tx] = ps1[ii];
        red2[(ty*4+ii)*16 + tx] = ps2[ii];
    }
    __syncthreads();
    if (tid < 64){
        float a = 0.f, b = 0.f;
        #pragma unroll
        for (int t = 0; t < 16; t++){ a += red1[tid*16 + t]; b += red2[tid*16 + t]; }
        int user = u0 + tid;
        if (user < NU){ s1[user] = a; s2[user] = b; }
    }
}

extern "C" void kernel_launch(void* const* d_in, const int* in_sizes, int n_in,
                              void* d_out, int out_size){
    const float* user_emb = (const float*)d_in[0];
    const float* item_emb = (const float*)d_in[1];
    const float* rel_emb  = (const float*)d_in[2];
    const float* W_gc     = (const float*)d_in[3];
    const float* W_rel    = (const float*)d_in[4];
    const float* gru_w    = (const float*)d_in[5];
    const float* gru_b    = (const float*)d_in[6];
    const float* tra      = (const float*)d_in[7];
    const float* adj_vals = (const float*)d_in[8];
    const int*   adj_rows = (const int*)  d_in[9];
    const int*   adj_cols = (const int*)  d_in[10];
    float* out = (float*)d_out;

    k_init<<<(NN*16 + 255)/256, 256>>>(user_emb, item_emb);
    k_rela<<<1, 64>>>(rel_emb, W_rel, out + OFF_RELA);
    k_zero_cnt<<<(RR*NN + 255)/256, 256>>>();
    k_bucket<<<dim3((EE/2)/256, 3), 256>>>(adj_vals, adj_rows, adj_cols);

    const float inv_sqrt = 0.08838834764831845f;  // 1/sqrt(128)
    for (int k = 0; k < 2; k++){
        k_gather<<<dim3(NN/16, 3), 256>>>();
        k_trans_attn<<<NN/32, 384>>>(W_gc + (size_t)k*4096, k, inv_sqrt);
    }
    k_final<<<((NN + 1)*32 + 255)/256, 256>>>(out);
    k_score<<<(NU + 63)/64, 256>>>(out, gru_w, gru_b, tra,
                                   out + OFF_S1, out + OFF_S2);
}

// round 5
// speedup vs baseline: 1.5303x; 1.0570x over previous
#include <cuda_runtime.h>
#include <cuda_bf16.h>
#include <cstdint>

#define NU 70000
#define NI 30000
#define NN 100000   // NU+NI
#define RR 3
#define DD 64
#define EE 1600000
#define CAP 64                 // bucket capacity per (rel,row)

// output layout (f32, flattened tuple)
#define OFF_U   ((size_t)0)
#define OFF_I   ((size_t)NU*192)                    // 13,440,000
#define OFF_RELA (OFF_I + (size_t)(NI+1)*192)       // 19,200,192
#define OFF_S1  (OFF_RELA + 192)                    // 19,200,384
#define OFF_S2  (OFF_S1 + NU)                       // 19,270,384

// -------- scratch (device globals; no allocation allowed) --------
__device__ float g_ego [(size_t)NN*RR*DD];
__device__ float g_all [(size_t)NN*RR*DD];
__device__ float g_rela[3*RR*DD];   // rela[0..2], each 3x64
__device__ int   g_cnt [RR*NN];
__device__ __align__(16) int2 g_bkt[(size_t)RR*NN*CAP];   // zero-init; unwritten slots stay (0, 0.0f)

__device__ __forceinline__ float lrelu(float x){ return x > 0.f ? x : 0.01f*x; }

// ---------------- rela chain + rela_out ----------------
__global__ void k_rela(const float* __restrict__ rel_emb,
                       const float* __restrict__ Wrel,
                       float* __restrict__ out_rela){
    __shared__ float s0[192], s1[192], s2[192];
    int j = threadIdx.x;                            // 64 threads
    #pragma unroll
    for (int i = 0; i < 3; i++) s0[i*64+j] = rel_emb[i*64+j];
    __syncthreads();
    #pragma unroll
    for (int i = 0; i < 3; i++){
        float a = 0.f;
        #pragma unroll
        for (int d = 0; d < 64; d++) a += s0[i*64+d]*Wrel[d*64+j];
        s1[i*64+j] = a;
    }
    __syncthreads();
    #pragma unroll
    for (int i = 0; i < 3; i++){
        float a = 0.f;
        #pragma unroll
        for (int d = 0; d < 64; d++) a += s1[i*64+d]*Wrel[4096 + d*64+j];
        s2[i*64+j] = a;
    }
    __syncthreads();
    #pragma unroll
    for (int i = 0; i < 3; i++){
        g_rela[        i*64+j] = s0[i*64+j];
        g_rela[192   + i*64+j] = s1[i*64+j];
        g_rela[384   + i*64+j] = s2[i*64+j];
        out_rela[i*64+j] = (s0[i*64+j] + s1[i*64+j] + s2[i*64+j]) * (1.f/3.f);
    }
}

// ---------------- zero bucket counters ----------------
__global__ __launch_bounds__(256) void k_zero_cnt(){
    int t = blockIdx.x*256 + threadIdx.x;
    if (t < RR*NN) g_cnt[t] = 0;
}

// ---------------- bucket build: per (rel,row) edge list, MLP=4 ----------------
#define EQ4 (EE/4)
__global__ __launch_bounds__(256) void k_bucket(const float* __restrict__ vals,
                                                const int*   __restrict__ rows,
                                                const int*   __restrict__ cols){
    int rel = blockIdx.y;
    int e   = blockIdx.x*256 + threadIdx.x;    // 0 .. EQ4-1
    if (e >= EQ4) return;
    int f[4], row[4], col[4];
    float v[4];
    #pragma unroll
    for (int q = 0; q < 4; q++) f[q] = rel*EE + e + q*EQ4;
    #pragma unroll
    for (int q = 0; q < 4; q++){
        row[q] = __ldg(rows + f[q]);
        col[q] = __ldg(cols + f[q]);
        v[q]   = __ldg(vals + f[q]);
    }
    int pos[4];
    #pragma unroll
    for (int q = 0; q < 4; q++)
        pos[q] = atomicAdd(&g_cnt[rel*NN + row[q]], 1);
    #pragma unroll
    for (int q = 0; q < 4; q++)
        if (pos[q] < CAP)
            g_bkt[((size_t)(rel*NN + row[q]))*CAP + pos[q]] = make_int2(col[q], __float_as_int(v[q]));
}

#define WARP_SUM(x) { _Pragma("unroll") for (int _o = 16; _o; _o >>= 1) x += __shfl_xor_sync(0xffffffffu, x, _o); }

// ---------------- fused layer: gather -> (.*rela)@Wgc -> lrelu -> attn -> ego/all ----
// block = 32 nodes = 96 (node,rel) rows, 384 threads
__global__ __launch_bounds__(384) void k_layer(const float* __restrict__ Wgc,
                                               int k, float scale,
                                               const float* __restrict__ ue,
                                               const float* __restrict__ ie){
    __shared__ __align__(16) float Ws[64*64];     // 16KB
    __shared__ __align__(16) float Abuf[6528];    // stage: [c*100 + rl] / est: 96x68
    __shared__ __align__(16) float srel[192];
    int tid = threadIdx.x;
    int n0  = blockIdx.x*32;

    #pragma unroll
    for (int i = 0; i < 3; i++){
        int idx = i*384 + tid;
        if (idx < 1024) ((float4*)Ws)[idx] = ((const float4*)Wgc)[idx];
    }
    if (tid < 192) srel[tid] = g_rela[k*192 + tid];
    __syncthreads();

    // ---- fused gather: 24 groups of 16 lanes, 4 rows each ----
    {
        int grp  = tid >> 4;            // 0..23
        int lane = tid & 15;
        #pragma unroll
        for (int j = 0; j < 4; j++){
            int rl  = grp*4 + j;        // 0..95
            int nd  = n0 + (rl/3);
            int rel = rl - (rl/3)*3;
            int seg = rel*NN + nd;
            int cnt = g_cnt[seg];
            if (cnt > CAP) cnt = CAP;
            const int2* bp = g_bkt + (size_t)seg*CAP;
            float4 acc = make_float4(0.f,0.f,0.f,0.f);
            for (int e = 0; e < cnt; e += 4){
                int4 pa = *(const int4*)(bp + e);       // slots >= cnt are (0,0) => no-op
                int4 pb = *(const int4*)(bp + e + 2);
                const float *s0, *s1, *s2, *s3;
                if (k == 0){
                    s0 = (pa.x < NU) ? ue + (size_t)pa.x*64 : ie + (size_t)(pa.x-NU)*64;
                    s1 = (pa.z < NU) ? ue + (size_t)pa.z*64 : ie + (size_t)(pa.z-NU)*64;
                    s2 = (pb.x < NU) ? ue + (size_t)pb.x*64 : ie + (size_t)(pb.x-NU)*64;
                    s3 = (pb.z < NU) ? ue + (size_t)pb.z*64 : ie + (size_t)(pb.z-NU)*64;
                } else {
                    s0 = g_ego + ((size_t)pa.x*3 + rel)*64;
                    s1 = g_ego + ((size_t)pa.z*3 + rel)*64;
                    s2 = g_ego + ((size_t)pb.x*3 + rel)*64;
                    s3 = g_ego + ((size_t)pb.z*3 + rel)*64;
                }
                float4 m0 = *(const float4*)(s0 + lane*4);
                float4 m1 = *(const float4*)(s1 + lane*4);
                float4 m2 = *(const float4*)(s2 + lane*4);
                float4 m3 = *(const float4*)(s3 + lane*4);
                float v0 = __int_as_float(pa.y), v1 = __int_as_float(pa.w);
                float v2 = __int_as_float(pb.y), v3 = __int_as_float(pb.w);
                acc.x = fmaf(m0.x, v0, fmaf(m1.x, v1, fmaf(m2.x, v2, fmaf(m3.x, v3, acc.x))));
                acc.y = fmaf(m0.y, v0, fmaf(m1.y, v1, fmaf(m2.y, v2, fmaf(m3.y, v3, acc.y))));
                acc.z = fmaf(m0.z, v0, fmaf(m1.z, v1, fmaf(m2.z, v2, fmaf(m3.z, v3, acc.z))));
                acc.w = fmaf(m0.w, v0, fmaf(m1.w, v1, fmaf(m2.w, v2, fmaf(m3.w, v3, acc.w))));
            }
            // stage A transposed with rela scaling: Abuf[c*100 + rl]
            int c0 = lane*4;
            Abuf[(c0+0)*100 + rl] = acc.x * srel[rel*64 + c0+0];
            Abuf[(c0+1)*100 + rl] = acc.y * srel[rel*64 + c0+1];
            Abuf[(c0+2)*100 + rl] = acc.z * srel[rel*64 + c0+2];
            Abuf[(c0+3)*100 + rl] = acc.w * srel[rel*64 + c0+3];
        }
    }
    __syncthreads();

    int tx = tid & 15, ty = tid >> 4;      // ty 0..23 (24*4=96 rows), tx*4 cols
    float acc[4][4] = {};
    #pragma unroll
    for (int d = 0; d < 64; d++){
        float4 a = *(const float4*)&Abuf[d*100 + ty*4];
        float4 b = *(const float4*)&Ws[d*64 + tx*4];
        float av[4] = {a.x,a.y,a.z,a.w};
        float bv[4] = {b.x,b.y,b.z,b.w};
        #pragma unroll
        for (int ii = 0; ii < 4; ii++)
            #pragma unroll
            for (int jj = 0; jj < 4; jj++)
                acc[ii][jj] += av[ii]*bv[jj];
    }
    __syncthreads();   // all reads of Abuf done; now reuse as est[96][68]
    #pragma unroll
    for (int ii = 0; ii < 4; ii++){
        float4 o;
        o.x = lrelu(acc[ii][0]); o.y = lrelu(acc[ii][1]);
        o.z = lrelu(acc[ii][2]); o.w = lrelu(acc[ii][3]);
        *(float4*)&Abuf[(ty*4 + ii)*68 + tx*4] = o;
    }
    __syncthreads();

    // attention: 12 warps cover 32 local nodes
    int warp = tid >> 5, lane = tid & 31;
    for (int ln = warp; ln < 32; ln += 12){
        int node = n0 + ln;
        float2 e0 = *(float2*)&Abuf[(3*ln + 0)*68 + lane*2];
        float2 e1 = *(float2*)&Abuf[(3*ln + 1)*68 + lane*2];
        float2 e2 = *(float2*)&Abuf[(3*ln + 2)*68 + lane*2];
        float g00 = e0.x*e0.x + e0.y*e0.y;
        float g01 = e0.x*e1.x + e0.y*e1.y;
        float g02 = e0.x*e2.x + e0.y*e2.y;
        float g11 = e1.x*e1.x + e1.y*e1.y;
        float g12 = e1.x*e2.x + e1.y*e2.y;
        float g22 = e2.x*e2.x + e2.y*e2.y;
        WARP_SUM(g00); WARP_SUM(g01); WARP_SUM(g02);
        WARP_SUM(g11); WARP_SUM(g12); WARP_SUM(g22);
        float G[3][3] = {{g00,g01,g02},{g01,g11,g12},{g02,g12,g22}};
        size_t base = (size_t)node*192 + lane*2;
        float2 em = make_float2(0.f, 0.f);
        if (k == 0){
            const float* ep = (node < NU) ? ue + (size_t)node*64 : ie + (size_t)(node-NU)*64;
            em = *(const float2*)(ep + lane*2);
        }
        #pragma unroll
        for (int r = 0; r < 3; r++){
            float l0 = G[r][0]*scale, l1 = G[r][1]*scale, l2 = G[r][2]*scale;
            float m = fmaxf(l0, fmaxf(l1, l2));
            float w0 = __expf(l0 - m), w1 = __expf(l1 - m), w2 = __expf(l2 - m);
            float inv = 1.f/(w0 + w1 + w2);
            w0 *= inv; w1 *= inv; w2 *= inv;
            float2 o;
            o.x = w0*e0.x + w1*e1.x + w2*e2.x;
            o.y = w0*e0.y + w1*e1.y + w2*e2.y;
            *(float2*)(g_ego + base + r*64) = o;
            float2 al;
            if (k == 0){                 // all = emb + ego  (write, no read)
                al.x = em.x + o.x; al.y = em.y + o.y;
            } else {                     // all += ego
                al = *(float2*)(g_all + base + r*64);
                al.x += o.x; al.y += o.y;
            }
            *(float2*)(g_all + base + r*64) = al;
        }
    }
}

// ---------------- final attention + write u / i_emb ----------------
__global__ __launch_bounds__(256) void k_final(float* __restrict__ out){
    int gw = (blockIdx.x*256 + threadIdx.x) >> 5;
    int lane = threadIdx.x & 31;
    if (gw > NN) return;
    if (gw == NN){  // padded zero row of i_emb
        float* dst = out + OFF_I + (size_t)NI*192 + lane*2;
        float2 z = make_float2(0.f, 0.f);
        #pragma unroll
        for (int r = 0; r < 3; r++) *(float2*)(dst + r*64) = z;
        return;
    }
    size_t base = (size_t)gw*192 + lane*2;
    float2 a0 = *(float2*)(g_all + base);
    float2 a1 = *(float2*)(g_all + base + 64);
    float2 a2 = *(float2*)(g_all + base + 128);
    float g20 = a2.x*a0.x + a2.y*a0.y;
    float g21 = a2.x*a1.x + a2.y*a1.y;
    float g22 = a2.x*a2.x + a2.y*a2.y;
    WARP_SUM(g20); WARP_SUM(g21); WARP_SUM(g22);
    float m = fmaxf(g20, fmaxf(g21, g22));
    float w0 = __expf(g20 - m), w1 = __expf(g21 - m), w2 = __expf(g22 - m);
    float inv = 1.f/(w0 + w1 + w2);
    w0 *= inv; w1 *= inv; w2 *= inv;
    float2 mid;
    mid.x = w0*a0.x + w1*a1.x + w2*a2.x;
    mid.y = w0*a0.y + w1*a1.y + w2*a2.y;
    const float third = 1.f/3.f;
    float* dst = (gw < NU) ? out + (size_t)gw*192 + lane*2
                           : out + OFF_I + (size_t)(gw-NU)*192 + lane*2;
    *(float2*)(dst)       = make_float2(a0.x*third, a0.y*third);
    *(float2*)(dst + 64)  = make_float2(a1.x*third, a1.y*third);
    *(float2*)(dst + 128) = make_float2(mid.x*third, mid.y*third);
}

// ---------------- GRU gates + scores ----------------
__global__ __launch_bounds__(256) void k_score(const float* __restrict__ u,
                                               const float* __restrict__ gru_w,
                                               const float* __restrict__ gru_b,
                                               const float* __restrict__ tra,
                                               float* __restrict__ s1,
                                               float* __restrict__ s2){
    __shared__ __align__(16) float Ws[64*64];
    __shared__ __align__(16) float As[64*68];
    __shared__ float red1[64*16];
    __shared__ float red2[64*16];
    int tid = threadIdx.x;
    int u0 = blockIdx.x*64;
    int tx = tid & 15, ty = tid >> 4;
    float ps1[4] = {}, ps2[4] = {};
    for (int r = 0; r < 3; r++){
        if (r) __syncthreads();
        #pragma unroll
        for (int i = 0; i < 4; i++)
            ((float4*)Ws)[tid + i*256] = ((const float4*)(gru_w + r*4096))[tid + i*256];
        #pragma unroll
        for (int i = 0; i < 16; i++){
            int flat = i*256 + tid;
            int ul = flat >> 6, c = flat & 63;
            int user = u0 + ul;
            As[c*68 + ul] = (user < NU) ? u[(size_t)user*192 + r*64 + c] : 0.f;
        }
        __syncthreads();
        float acc[4][4] = {};
        #pragma unroll
        for (int d = 0; d < 64; d++){
            float4 a = *(const float4*)&As[d*68 + ty*4];
            float4 b = *(const float4*)&Ws[d*64 + tx*4];
            float av[4] = {a.x,a.y,a.z,a.w};
            float bv[4] = {b.x,b.y,b.z,b.w};
            #pragma unroll
            for (int ii = 0; ii < 4; ii++)
                #pragma unroll
                for (int jj = 0; jj < 4; jj++)
                    acc[ii][jj] += av[ii]*bv[jj];
        }
        #pragma unroll
        for (int ii = 0; ii < 4; ii++){
            #pragma unroll
            for (int jj = 0; jj < 4; jj++){
                int j = tx*4 + jj;
                float uval = As[j*68 + ty*4 + ii];
                float h = uval * (acc[ii][jj] + __ldg(gru_b + r*64 + j));
                if (r == 2){       // tgt feeds both scores
                    ps1[ii] += h*__ldg(tra + j);
                    ps2[ii] += h*__ldg(tra + 128 + j);
                } else if (r == 0){
                    ps1[ii] += h*__ldg(tra + 64 + j);
                } else {
                    ps2[ii] += h*__ldg(tra + 128 + 64 + j);
                }
            }
        }
    }
    __syncthreads();
    #pragma unroll
    for (int ii = 0; ii < 4; ii++){
        red1[(ty*4+ii)*16 + tx] = ps1[ii];
        red2[(ty*4+ii)*16 + tx] = ps2[ii];
    }
    __syncthreads();
    if (tid < 64){
        float a = 0.f, b = 0.f;
        #pragma unroll
        for (int t = 0; t < 16; t++){ a += red1[tid*16 + t]; b += red2[tid*16 + t]; }
        int user = u0 + tid;
        if (user < NU){ s1[user] = a; s2[user] = b; }
    }
}

extern "C" void kernel_launch(void* const* d_in, const int* in_sizes, int n_in,
                              void* d_out, int out_size){
    const float* user_emb = (const float*)d_in[0];
    const float* item_emb = (const float*)d_in[1];
    const float* rel_emb  = (const float*)d_in[2];
    const float* W_gc     = (const float*)d_in[3];
    const float* W_rel    = (const float*)d_in[4];
    const float* gru_w    = (const float*)d_in[5];
    const float* gru_b    = (const float*)d_in[6];
    const float* tra      = (const float*)d_in[7];
    const float* adj_vals = (const float*)d_in[8];
    const int*   adj_rows = (const int*)  d_in[9];
    const int*   adj_cols = (const int*)  d_in[10];
    float* out = (float*)d_out;

    k_rela<<<1, 64>>>(rel_emb, W_rel, out + OFF_RELA);
    k_zero_cnt<<<(RR*NN + 255)/256, 256>>>();
    k_bucket<<<dim3((EQ4 + 255)/256, 3), 256>>>(adj_vals, adj_rows, adj_cols);

    const float inv_sqrt = 0.08838834764831845f;  // 1/sqrt(128)
    for (int k = 0; k < 2; k++){
        k_layer<<<NN/32, 384>>>(W_gc + (size_t)k*4096, k, inv_sqrt,
                                user_emb, item_emb);
    }
    k_final<<<((NN + 1)*32 + 255)/256, 256>>>(out);
    k_score<<<(NU + 63)/64, 256>>>(out, gru_w, gru_b, tra,
                                   out + OFF_S1, out + OFF_S2);
}

// round 6
// speedup vs baseline: 1.6462x; 1.0757x over previous
#include <cuda_runtime.h>
#include <cuda_bf16.h>
#include <cstdint>

#define NU 70000
#define NI 30000
#define NN 100000   // NU+NI
#define RR 3
#define DD 64
#define EE 1600000
#define CAP 64                 // bucket capacity per (rel,row)

// output layout (f32, flattened tuple)
#define OFF_U   ((size_t)0)
#define OFF_I   ((size_t)NU*192)                    // 13,440,000
#define OFF_RELA (OFF_I + (size_t)(NI+1)*192)       // 19,200,192
#define OFF_S1  (OFF_RELA + 192)                    // 19,200,384
#define OFF_S2  (OFF_S1 + NU)                       // 19,270,384

// -------- scratch (device globals; no allocation allowed) --------
__device__ float g_ego [(size_t)NN*RR*DD];
__device__ float g_all [(size_t)NN*RR*DD];
__device__ float g_rela[3*RR*DD];   // rela[0..2], each 3x64
__device__ int   g_cnt [RR*NN];
__device__ __align__(16) int2 g_bkt[(size_t)RR*NN*CAP];   // zero-init; unwritten slots stay (0, 0.0f)

__device__ __forceinline__ float lrelu(float x){ return x > 0.f ? x : 0.01f*x; }

// ---------------- rela chain + rela_out + i_emb pad row ----------------
__global__ void k_rela(const float* __restrict__ rel_emb,
                       const float* __restrict__ Wrel,
                       float* __restrict__ out){
    __shared__ float s0[192], s1[192], s2[192];
    int j = threadIdx.x;                            // 64 threads
    // zero pad row of i_emb (row NI)
    float* pad = out + OFF_I + (size_t)NI*192;
    #pragma unroll
    for (int i = 0; i < 3; i++) pad[i*64 + j] = 0.f;
    float* out_rela = out + OFF_RELA;
    #pragma unroll
    for (int i = 0; i < 3; i++) s0[i*64+j] = rel_emb[i*64+j];
    __syncthreads();
    #pragma unroll
    for (int i = 0; i < 3; i++){
        float a = 0.f;
        #pragma unroll
        for (int d = 0; d < 64; d++) a += s0[i*64+d]*Wrel[d*64+j];
        s1[i*64+j] = a;
    }
    __syncthreads();
    #pragma unroll
    for (int i = 0; i < 3; i++){
        float a = 0.f;
        #pragma unroll
        for (int d = 0; d < 64; d++) a += s1[i*64+d]*Wrel[4096 + d*64+j];
        s2[i*64+j] = a;
    }
    __syncthreads();
    #pragma unroll
    for (int i = 0; i < 3; i++){
        g_rela[        i*64+j] = s0[i*64+j];
        g_rela[192   + i*64+j] = s1[i*64+j];
        g_rela[384   + i*64+j] = s2[i*64+j];
        out_rela[i*64+j] = (s0[i*64+j] + s1[i*64+j] + s2[i*64+j]) * (1.f/3.f);
    }
}

// ---------------- zero bucket counters ----------------
__global__ __launch_bounds__(256) void k_zero_cnt(){
    int t = blockIdx.x*256 + threadIdx.x;
    if (t < RR*NN) g_cnt[t] = 0;
}

// ---------------- bucket build: per (rel,row) edge list, MLP=8 ----------------
#define EQ8 (EE/8)
__global__ __launch_bounds__(256) void k_bucket(const float* __restrict__ vals,
                                                const int*   __restrict__ rows,
                                                const int*   __restrict__ cols){
    int rel = blockIdx.y;
    int e   = blockIdx.x*256 + threadIdx.x;    // 0 .. EQ8-1
    if (e >= EQ8) return;
    int f[8], row[8], col[8];
    float v[8];
    #pragma unroll
    for (int q = 0; q < 8; q++) f[q] = rel*EE + e + q*EQ8;
    #pragma unroll
    for (int q = 0; q < 8; q++){
        row[q] = __ldg(rows + f[q]);
        col[q] = __ldg(cols + f[q]);
        v[q]   = __ldg(vals + f[q]);
    }
    int pos[8];
    #pragma unroll
    for (int q = 0; q < 8; q++)
        pos[q] = atomicAdd(&g_cnt[rel*NN + row[q]], 1);
    #pragma unroll
    for (int q = 0; q < 8; q++)
        if (pos[q] < CAP)
            g_bkt[((size_t)(rel*NN + row[q]))*CAP + pos[q]] = make_int2(col[q], __float_as_int(v[q]));
}

#define WARP_SUM(x) { _Pragma("unroll") for (int _o = 16; _o; _o >>= 1) x += __shfl_xor_sync(0xffffffffu, x, _o); }

// ---------------- fused layer: gather -> (.*rela)@Wgc -> lrelu -> attn ----------
// k=0: ego/all written.  k=1: final attention fused, writes u/i_emb to out.
// block = 32 nodes = 96 (node,rel) rows, 384 threads
__global__ __launch_bounds__(384, 4) void k_layer(const float* __restrict__ Wgc,
                                                  int k, float scale,
                                                  const float* __restrict__ ue,
                                                  const float* __restrict__ ie,
                                                  float* __restrict__ out){
    __shared__ __align__(16) float Ws[64*64];     // 16KB
    __shared__ __align__(16) float Abuf[6528];    // stage: [c*100 + rl] / est: 96x68
    __shared__ __align__(16) float srel[192];
    int tid = threadIdx.x;
    int n0  = blockIdx.x*32;

    #pragma unroll
    for (int i = 0; i < 3; i++){
        int idx = i*384 + tid;
        if (idx < 1024) ((float4*)Ws)[idx] = ((const float4*)Wgc)[idx];
    }
    if (tid < 192) srel[tid] = g_rela[k*192 + tid];
    __syncthreads();

    // ---- fused gather: 24 groups of 16 lanes, 4 rows each ----
    {
        int grp  = tid >> 4;            // 0..23
        int lane = tid & 15;
        #pragma unroll
        for (int j = 0; j < 4; j++){
            int rl  = grp*4 + j;        // 0..95
            int nd  = n0 + (rl/3);
            int rel = rl - (rl/3)*3;
            int seg = rel*NN + nd;
            int cnt = g_cnt[seg];
            if (cnt > CAP) cnt = CAP;
            const int2* bp = g_bkt + (size_t)seg*CAP;
            float4 acc = make_float4(0.f,0.f,0.f,0.f);
            for (int e = 0; e < cnt; e += 4){
                int4 pa = *(const int4*)(bp + e);       // slots >= cnt are (0,0) => no-op
                int4 pb = *(const int4*)(bp + e + 2);
                const float *s0, *s1, *s2, *s3;
                if (k == 0){
                    s0 = (pa.x < NU) ? ue + (size_t)pa.x*64 : ie + (size_t)(pa.x-NU)*64;
                    s1 = (pa.z < NU) ? ue + (size_t)pa.z*64 : ie + (size_t)(pa.z-NU)*64;
                    s2 = (pb.x < NU) ? ue + (size_t)pb.x*64 : ie + (size_t)(pb.x-NU)*64;
                    s3 = (pb.z < NU) ? ue + (size_t)pb.z*64 : ie + (size_t)(pb.z-NU)*64;
                } else {
                    s0 = g_ego + ((size_t)pa.x*3 + rel)*64;
                    s1 = g_ego + ((size_t)pa.z*3 + rel)*64;
                    s2 = g_ego + ((size_t)pb.x*3 + rel)*64;
                    s3 = g_ego + ((size_t)pb.z*3 + rel)*64;
                }
                float4 m0 = *(const float4*)(s0 + lane*4);
                float4 m1 = *(const float4*)(s1 + lane*4);
                float4 m2 = *(const float4*)(s2 + lane*4);
                float4 m3 = *(const float4*)(s3 + lane*4);
                float v0 = __int_as_float(pa.y), v1 = __int_as_float(pa.w);
                float v2 = __int_as_float(pb.y), v3 = __int_as_float(pb.w);
                acc.x = fmaf(m0.x, v0, fmaf(m1.x, v1, fmaf(m2.x, v2, fmaf(m3.x, v3, acc.x))));
                acc.y = fmaf(m0.y, v0, fmaf(m1.y, v1, fmaf(m2.y, v2, fmaf(m3.y, v3, acc.y))));
                acc.z = fmaf(m0.z, v0, fmaf(m1.z, v1, fmaf(m2.z, v2, fmaf(m3.z, v3, acc.z))));
                acc.w = fmaf(m0.w, v0, fmaf(m1.w, v1, fmaf(m2.w, v2, fmaf(m3.w, v3, acc.w))));
            }
            // stage A transposed with rela scaling: Abuf[c*100 + rl]
            int c0 = lane*4;
            Abuf[(c0+0)*100 + rl] = acc.x * srel[rel*64 + c0+0];
            Abuf[(c0+1)*100 + rl] = acc.y * srel[rel*64 + c0+1];
            Abuf[(c0+2)*100 + rl] = acc.z * srel[rel*64 + c0+2];
            Abuf[(c0+3)*100 + rl] = acc.w * srel[rel*64 + c0+3];
        }
    }
    __syncthreads();

    int tx = tid & 15, ty = tid >> 4;      // ty 0..23 (24*4=96 rows), tx*4 cols
    float acc[4][4] = {};
    #pragma unroll
    for (int d = 0; d < 64; d++){
        float4 a = *(const float4*)&Abuf[d*100 + ty*4];
        float4 b = *(const float4*)&Ws[d*64 + tx*4];
        float av[4] = {a.x,a.y,a.z,a.w};
        float bv[4] = {b.x,b.y,b.z,b.w};
        #pragma unroll
        for (int ii = 0; ii < 4; ii++)
            #pragma unroll
            for (int jj = 0; jj < 4; jj++)
                acc[ii][jj] += av[ii]*bv[jj];
    }
    __syncthreads();   // all reads of Abuf done; now reuse as est[96][68]
    #pragma unroll
    for (int ii = 0; ii < 4; ii++){
        float4 o;
        o.x = lrelu(acc[ii][0]); o.y = lrelu(acc[ii][1]);
        o.z = lrelu(acc[ii][2]); o.w = lrelu(acc[ii][3]);
        *(float4*)&Abuf[(ty*4 + ii)*68 + tx*4] = o;
    }
    __syncthreads();

    // attention: 12 warps cover 32 local nodes
    int warp = tid >> 5, lane = tid & 31;
    for (int ln = warp; ln < 32; ln += 12){
        int node = n0 + ln;
        float2 e0 = *(float2*)&Abuf[(3*ln + 0)*68 + lane*2];
        float2 e1 = *(float2*)&Abuf[(3*ln + 1)*68 + lane*2];
        float2 e2 = *(float2*)&Abuf[(3*ln + 2)*68 + lane*2];
        float g00 = e0.x*e0.x + e0.y*e0.y;
        float g01 = e0.x*e1.x + e0.y*e1.y;
        float g02 = e0.x*e2.x + e0.y*e2.y;
        float g11 = e1.x*e1.x + e1.y*e1.y;
        float g12 = e1.x*e2.x + e1.y*e2.y;
        float g22 = e2.x*e2.x + e2.y*e2.y;
        WARP_SUM(g00); WARP_SUM(g01); WARP_SUM(g02);
        WARP_SUM(g11); WARP_SUM(g12); WARP_SUM(g22);
        float G[3][3] = {{g00,g01,g02},{g01,g11,g12},{g02,g12,g22}};
        size_t base = (size_t)node*192 + lane*2;
        float2 al[3];
        if (k == 0){
            const float* ep = (node < NU) ? ue + (size_t)node*64 : ie + (size_t)(node-NU)*64;
            float2 em = *(const float2*)(ep + lane*2);
            #pragma unroll
            for (int r = 0; r < 3; r++){
                float l0 = G[r][0]*scale, l1 = G[r][1]*scale, l2 = G[r][2]*scale;
                float m = fmaxf(l0, fmaxf(l1, l2));
                float w0 = __expf(l0 - m), w1 = __expf(l1 - m), w2 = __expf(l2 - m);
                float inv = 1.f/(w0 + w1 + w2);
                w0 *= inv; w1 *= inv; w2 *= inv;
                float2 o;
                o.x = w0*e0.x + w1*e1.x + w2*e2.x;
                o.y = w0*e0.y + w1*e1.y + w2*e2.y;
                *(float2*)(g_ego + base + r*64) = o;                  // feeds layer-1 gather
                float2 a = make_float2(em.x + o.x, em.y + o.y);       // all = emb + ego
                *(float2*)(g_all + base + r*64) = a;
            }
        } else {
            #pragma unroll
            for (int r = 0; r < 3; r++){
                float l0 = G[r][0]*scale, l1 = G[r][1]*scale, l2 = G[r][2]*scale;
                float m = fmaxf(l0, fmaxf(l1, l2));
                float w0 = __expf(l0 - m), w1 = __expf(l1 - m), w2 = __expf(l2 - m);
                float inv = 1.f/(w0 + w1 + w2);
                w0 *= inv; w1 *= inv; w2 *= inv;
                float2 o;
                o.x = w0*e0.x + w1*e1.x + w2*e2.x;
                o.y = w0*e0.y + w1*e1.y + w2*e2.y;
                float2 a = *(float2*)(g_all + base + r*64);           // all += ego (in regs)
                al[r] = make_float2(a.x + o.x, a.y + o.y);
            }
            // fused final attention (no scale), query = row 2
            float g20 = al[2].x*al[0].x + al[2].y*al[0].y;
            float g21 = al[2].x*al[1].x + al[2].y*al[1].y;
            float g22f = al[2].x*al[2].x + al[2].y*al[2].y;
            WARP_SUM(g20); WARP_SUM(g21); WARP_SUM(g22f);
            float m = fmaxf(g20, fmaxf(g21, g22f));
            float w0 = __expf(g20 - m), w1 = __expf(g21 - m), w2 = __expf(g22f - m);
            float inv = 1.f/(w0 + w1 + w2);
            w0 *= inv; w1 *= inv; w2 *= inv;
            float2 mid;
            mid.x = w0*al[0].x + w1*al[1].x + w2*al[2].x;
            mid.y = w0*al[0].y + w1*al[1].y + w2*al[2].y;
            const float third = 1.f/3.f;
            float* dst = (node < NU) ? out + (size_t)node*192 + lane*2
                                     : out + OFF_I + (size_t)(node-NU)*192 + lane*2;
            *(float2*)(dst)       = make_float2(al[0].x*third, al[0].y*third);
            *(float2*)(dst + 64)  = make_float2(al[1].x*third, al[1].y*third);
            *(float2*)(dst + 128) = make_float2(mid.x*third, mid.y*third);
        }
    }
}

// ---------------- GRU gates + scores ----------------
__global__ __launch_bounds__(256) void k_score(const float* __restrict__ u,
                                               const float* __restrict__ gru_w,
                                               const float* __restrict__ gru_b,
                                               const float* __restrict__ tra,
                                               float* __restrict__ s1,
                                               float* __restrict__ s2){
    __shared__ __align__(16) float Ws[64*64];
    __shared__ __align__(16) float As[64*68];
    __shared__ float red1[64*16];
    __shared__ float red2[64*16];
    int tid = threadIdx.x;
    int u0 = blockIdx.x*64;
    int tx = tid & 15, ty = tid >> 4;
    float ps1[4] = {}, ps2[4] = {};
    for (int r = 0; r < 3; r++){
        if (r) __syncthreads();
        #pragma unroll
        for (int i = 0; i < 4; i++)
            ((float4*)Ws)[tid + i*256] = ((const float4*)(gru_w + r*4096))[tid + i*256];
        #pragma unroll
        for (int i = 0; i < 16; i++){
            int flat = i*256 + tid;
            int ul = flat >> 6, c = flat & 63;
            int user = u0 + ul;
            As[c*68 + ul] = (user < NU) ? u[(size_t)user*192 + r*64 + c] : 0.f;
        }
        __syncthreads();
        float acc[4][4] = {};
        #pragma unroll
        for (int d = 0; d < 64; d++){
            float4 a = *(const float4*)&As[d*68 + ty*4];
            float4 b = *(const float4*)&Ws[d*64 + tx*4];
            float av[4] = {a.x,a.y,a.z,a.w};
            float bv[4] = {b.x,b.y,b.z,b.w};
            #pragma unroll
            for (int ii = 0; ii < 4; ii++)
                #pragma unroll
                for (int jj = 0; jj < 4; jj++)
                    acc[ii][jj] += av[ii]*bv[jj];
        }
        #pragma unroll
        for (int ii = 0; ii < 4; ii++){
            #pragma unroll
            for (int jj = 0; jj < 4; jj++){
                int j = tx*4 + jj;
                float uval = As[j*68 + ty*4 + ii];
                float h = uval * (acc[ii][jj] + __ldg(gru_b + r*64 + j));
                if (r == 2){       // tgt feeds both scores
                    ps1[ii] += h*__ldg(tra + j);
                    ps2[ii] += h*__ldg(tra + 128 + j);
                } else if (r == 0){
                    ps1[ii] += h*__ldg(tra + 64 + j);
                } else {
                    ps2[ii] += h*__ldg(tra + 128 + 64 + j);
                }
            }
        }
    }
    __syncthreads();
    #pragma unroll
    for (int ii = 0; ii < 4; ii++){
        red1[(ty*4+ii)*16 + tx] = ps1[ii];
        red2[(ty*4+ii)*16 + tx] = ps2[ii];
    }
    __syncthreads();
    if (tid < 64){
        float a = 0.f, b = 0.f;
        #pragma unroll
        for (int t = 0; t < 16; t++){ a += red1[tid*16 + t]; b += red2[tid*16 + t]; }
        int user = u0 + tid;
        if (user < NU){ s1[user] = a; s2[user] = b; }
    }
}

extern "C" void kernel_launch(void* const* d_in, const int* in_sizes, int n_in,
                              void* d_out, int out_size){
    const float* user_emb = (const float*)d_in[0];
    const float* item_emb = (const float*)d_in[1];
    const float* rel_emb  = (const float*)d_in[2];
    const float* W_gc     = (const float*)d_in[3];
    const float* W_rel    = (const float*)d_in[4];
    const float* gru_w    = (const float*)d_in[5];
    const float* gru_b    = (const float*)d_in[6];
    const float* tra      = (const float*)d_in[7];
    const float* adj_vals = (const float*)d_in[8];
    const int*   adj_rows = (const int*)  d_in[9];
    const int*   adj_cols = (const int*)  d_in[10];
    float* out = (float*)d_out;

    k_rela<<<1, 64>>>(rel_emb, W_rel, out);
    k_zero_cnt<<<(RR*NN + 255)/256, 256>>>();
    k_bucket<<<dim3((EQ8 + 255)/256, 3), 256>>>(adj_vals, adj_rows, adj_cols);

    const float inv_sqrt = 0.08838834764831845f;  // 1/sqrt(128)
    for (int k = 0; k < 2; k++){
        k_layer<<<NN/32, 384>>>(W_gc + (size_t)k*4096, k, inv_sqrt,
                                user_emb, item_emb, out);
    }
    k_score<<<(NU + 63)/64, 256>>>(out, gru_w, gru_b, tra,
                                   out + OFF_S1, out + OFF_S2);
}